// round 12
// baseline (speedup 1.0000x reference)
#include <cuda_runtime.h>
#include <cuda_bf16.h>
#include <cstdint>
#include <cstddef>

// ---------------------------------------------------------------------------
// Problem constants
// ---------------------------------------------------------------------------
constexpr int B_  = 2;
constexpr int S_  = 2048;
constexpr int D_  = 1024;
constexpr int H_  = 16;
constexpr int DH_ = 64;
constexpr int M_  = B_ * S_;   // 4096

// ---------------------------------------------------------------------------
// Scratch: pre-split bf16 hi/lo pairs (16B-aligned for cp.async)
// ---------------------------------------------------------------------------
__device__ __align__(256) __nv_bfloat16 g_xh[(size_t)M_ * D_], g_xl[(size_t)M_ * D_];
__device__ __align__(256) __nv_bfloat16 g_wh[4][(size_t)D_ * D_], g_wl[4][(size_t)D_ * D_];
__device__ __align__(256) __nv_bfloat16 g_qkvh[3][(size_t)M_ * D_], g_qkvl[3][(size_t)M_ * D_];
__device__ __align__(256) __nv_bfloat16 g_aoh[(size_t)M_ * D_], g_aol[(size_t)M_ * D_];

// ---------------------------------------------------------------------------
// Helpers
// ---------------------------------------------------------------------------
__device__ __forceinline__ void mma16816(float* c, const uint32_t* a, const uint32_t* b) {
    asm volatile(
        "mma.sync.aligned.m16n8k16.row.col.f32.bf16.bf16.f32 "
        "{%0,%1,%2,%3}, {%4,%5,%6,%7}, {%8,%9}, {%0,%1,%2,%3};"
        : "+f"(c[0]), "+f"(c[1]), "+f"(c[2]), "+f"(c[3])
        : "r"(a[0]), "r"(a[1]), "r"(a[2]), "r"(a[3]), "r"(b[0]), "r"(b[1]));
}

__device__ __forceinline__ void split2(float x, float y, uint32_t& hi, uint32_t& lo) {
    __nv_bfloat162 h = __floats2bfloat162_rn(x, y);
    float rx = x - __bfloat162float(h.x);
    float ry = y - __bfloat162float(h.y);
    __nv_bfloat162 l = __floats2bfloat162_rn(rx, ry);
    hi = *reinterpret_cast<uint32_t*>(&h);
    lo = *reinterpret_cast<uint32_t*>(&l);
}

__device__ __forceinline__ uint32_t smem_u32(const void* p) {
    uint32_t a;
    asm("{ .reg .u64 t; cvta.to.shared.u64 t, %1; cvt.u32.u64 %0, t; }" : "=r"(a) : "l"(p));
    return a;
}

__device__ __forceinline__ void ldsm4(uint32_t* r, uint32_t addr) {
    asm volatile("ldmatrix.sync.aligned.m8n8.x4.shared.b16 {%0,%1,%2,%3}, [%4];"
        : "=r"(r[0]), "=r"(r[1]), "=r"(r[2]), "=r"(r[3]) : "r"(addr));
}
__device__ __forceinline__ void ldsm4t(uint32_t* r, uint32_t addr) {
    asm volatile("ldmatrix.sync.aligned.m8n8.x4.trans.shared.b16 {%0,%1,%2,%3}, [%4];"
        : "=r"(r[0]), "=r"(r[1]), "=r"(r[2]), "=r"(r[3]) : "r"(addr));
}

__device__ __forceinline__ void cp16(uint32_t saddr, const void* g) {
    asm volatile("cp.async.cg.shared.global [%0], [%1], 16;" :: "r"(saddr), "l"(g));
}
__device__ __forceinline__ void cp_commit() { asm volatile("cp.async.commit_group;"); }
template <int N> __device__ __forceinline__ void cp_wait() {
    asm volatile("cp.async.wait_group %0;" :: "n"(N));
}

// ---------------------------------------------------------------------------
// Fused fp32 -> bf16 hi/lo splitter
// ---------------------------------------------------------------------------
__global__ void split_all(const float4* __restrict__ x,
                          const float4* __restrict__ w0, const float4* __restrict__ w1,
                          const float4* __restrict__ w2, const float4* __restrict__ w3,
                          uint2* __restrict__ xh, uint2* __restrict__ xl,
                          uint2* __restrict__ wh, uint2* __restrict__ wl)
{
    const int i = blockIdx.x * blockDim.x + threadIdx.x;
    constexpr int NX = M_ * D_ / 4;
    constexpr int NW = D_ * D_ / 4;

    const float4* src;
    uint2 *dh, *dl;
    if (i < NX) {
        src = x + i; dh = xh + i; dl = xl + i;
    } else {
        const int j = i - NX;
        const int wsel = j / NW;
        const int k = j - wsel * NW;
        const float4* ws[4] = {w0, w1, w2, w3};
        src = ws[wsel] + k;
        dh = wh + (size_t)wsel * NW + k;
        dl = wl + (size_t)wsel * NW + k;
    }
    float4 f = *src;
    uint32_t h01, l01, h23, l23;
    split2(f.x, f.y, h01, l01);
    split2(f.z, f.w, h23, l23);
    *dh = make_uint2(h01, h23);
    *dl = make_uint2(l01, l23);
}

// ---------------------------------------------------------------------------
// GEMM (Round-8 best config): tile 128x128x32, 8 warps, warp 64x32,
// cp.async 2-stage, one barrier per k-iter, 2 CTAs/SM.
// MODE 0: fused QKV (blockIdx.x>>3 selects weight), scatter bf16 hi/lo;
//         Q output (wsel==0) pre-scaled by 0.125 (softmax scale).
// MODE 1: single weight, fp32 row-major output.
// ---------------------------------------------------------------------------
constexpr int RS = 40;
constexpr int GEMM_TILE_BF16 = 128 * RS;
constexpr int GEMM_SMEM = 2 * 4 * GEMM_TILE_BF16 * 2;    // 81920 B

template <int MODE>
__global__ __launch_bounds__(256, 2)
void gemm_bf16(const __nv_bfloat16* __restrict__ Ah_g, const __nv_bfloat16* __restrict__ Al_g,
               const __nv_bfloat16* __restrict__ Wh0, const __nv_bfloat16* __restrict__ Wl0,
               __nv_bfloat16* __restrict__ Oh0, __nv_bfloat16* __restrict__ Ol0,
               float* __restrict__ Of)
{
    extern __shared__ __nv_bfloat16 smem[];

    const int tid  = threadIdx.x;
    const int wid  = tid >> 5;
    const int lane = tid & 31;
    const int wm   = wid >> 2;
    const int wn   = wid & 3;
    const int lq   = lane >> 2;
    const int lr   = (lane & 3) << 1;

    int wsel, bn;
    if (MODE == 0) { wsel = blockIdx.x >> 3; bn = (blockIdx.x & 7) * 128; }
    else           { wsel = 0;               bn = blockIdx.x * 128; }
    const int bm = blockIdx.y * 128;

    const __nv_bfloat16* Bh_g = Wh0 + (size_t)wsel * D_ * D_;
    const __nv_bfloat16* Bl_g = Wl0 + (size_t)wsel * D_ * D_;

    const uint32_t sbase = smem_u32(smem);

    auto issue = [&](int k0, int s) {
#pragma unroll
        for (int i = 0; i < 8; ++i) {
            const int a    = i >> 1;
            const int c    = (i & 1) * 256 + tid;
            const int row  = c >> 2;
            const int c16  = c & 3;
            const size_t go = (size_t)((a < 2 ? bm : bn) + row) * D_ + k0 + c16 * 8;
            const __nv_bfloat16* g =
                (a == 0) ? Ah_g + go : (a == 1) ? Al_g + go :
                (a == 2) ? Bh_g + go : Bl_g + go;
            const uint32_t sa = sbase + (uint32_t)(((s * 4 + a) * GEMM_TILE_BF16
                                 + row * RS) * 2 + c16 * 16);
            cp16(sa, g);
        }
        cp_commit();
    };

    float acc[4][4][4];
#pragma unroll
    for (int i = 0; i < 4; i++)
#pragma unroll
        for (int j = 0; j < 4; j++)
#pragma unroll
            for (int r = 0; r < 4; r++) acc[i][j][r] = 0.0f;

    issue(0, 0);

    for (int kt = 0; kt < 32; ++kt) {
        const int s = kt & 1;
        cp_wait<0>();
        __syncthreads();
        if (kt < 31) issue((kt + 1) * 32, s ^ 1);

        const __nv_bfloat16* Ahs = smem + (s * 4 + 0) * GEMM_TILE_BF16;
        const __nv_bfloat16* Als = smem + (s * 4 + 1) * GEMM_TILE_BF16;
        const __nv_bfloat16* Bhs = smem + (s * 4 + 2) * GEMM_TILE_BF16;
        const __nv_bfloat16* Bls = smem + (s * 4 + 3) * GEMM_TILE_BF16;

#pragma unroll
        for (int ks = 0; ks < 2; ++ks) {
            const int kb = ks * 16 + lr;

            uint32_t bh[4][2], bl[4][2];
#pragma unroll
            for (int nt = 0; nt < 4; ++nt) {
                const int n = wn * 32 + nt * 8 + lq;
                bh[nt][0] = *(const uint32_t*)&Bhs[n * RS + kb];
                bh[nt][1] = *(const uint32_t*)&Bhs[n * RS + kb + 8];
                bl[nt][0] = *(const uint32_t*)&Bls[n * RS + kb];
                bl[nt][1] = *(const uint32_t*)&Bls[n * RS + kb + 8];
            }

#pragma unroll
            for (int mt = 0; mt < 4; ++mt) {
                const int r = wm * 64 + mt * 16 + lq;
                uint32_t ah[4], al[4];
                ah[0] = *(const uint32_t*)&Ahs[r * RS + kb];
                ah[1] = *(const uint32_t*)&Ahs[(r + 8) * RS + kb];
                ah[2] = *(const uint32_t*)&Ahs[r * RS + kb + 8];
                ah[3] = *(const uint32_t*)&Ahs[(r + 8) * RS + kb + 8];
                al[0] = *(const uint32_t*)&Als[r * RS + kb];
                al[1] = *(const uint32_t*)&Als[(r + 8) * RS + kb];
                al[2] = *(const uint32_t*)&Als[r * RS + kb + 8];
                al[3] = *(const uint32_t*)&Als[(r + 8) * RS + kb + 8];
#pragma unroll
                for (int nt = 0; nt < 4; ++nt) {
                    mma16816(acc[mt][nt], ah, bh[nt]);
                    mma16816(acc[mt][nt], ah, bl[nt]);
                    mma16816(acc[mt][nt], al, bh[nt]);
                }
            }
        }
    }

    __nv_bfloat16* Oh = (MODE == 0) ? Oh0 + (size_t)wsel * M_ * D_ : nullptr;
    __nv_bfloat16* Ol = (MODE == 0) ? Ol0 + (size_t)wsel * M_ * D_ : nullptr;
    const float oscale = (MODE == 0 && wsel == 0) ? 0.125f : 1.0f;

#pragma unroll
    for (int mt = 0; mt < 4; ++mt) {
#pragma unroll
        for (int nt = 0; nt < 4; ++nt) {
            const int n  = bn + wn * 32 + nt * 8 + lr;
            const int m0 = bm + wm * 64 + mt * 16 + lq;
#pragma unroll
            for (int half = 0; half < 2; ++half) {
                const int m = m0 + half * 8;
                const float v0 = acc[mt][nt][half * 2] * oscale;
                const float v1 = acc[mt][nt][half * 2 + 1] * oscale;
                if (MODE == 0) {
                    const int b_ = m >> 11;
                    const int s_ = m & 2047;
                    const int h_ = n >> 6;
                    const int d_ = n & 63;
                    const size_t off = (((size_t)(b_ * H_ + h_) * S_ + s_) << 6) + d_;
                    uint32_t hh, ll;
                    split2(v0, v1, hh, ll);
                    *(uint32_t*)&Oh[off] = hh;
                    *(uint32_t*)&Ol[off] = ll;
                } else {
                    *(float2*)&Of[(size_t)m * D_ + n] = make_float2(v0, v1);
                }
            }
        }
    }
}

// ---------------------------------------------------------------------------
// Flash attention: cp.async 3-stage K/V pipeline, one barrier per tile.
// NOW 2 CTAs/SM (launch_bounds(256,2); smem 110.6KB x2 = 221KB fits 227KB).
// Q fragments reloaded from gmem per tile (L1-resident) to fit 128 regs.
// Q is pre-scaled by 0.125 in the projection, so no scale multiply here.
// ---------------------------------------------------------------------------
constexpr int ARS = 72;
constexpr int ATT_TILE_BF16 = 64 * ARS;
constexpr int ATT_SMEM = 3 * 4 * ATT_TILE_BF16 * 2;   // 110592 B

__global__ __launch_bounds__(256, 2)
void attn_mma(const __nv_bfloat16* __restrict__ Qh_g, const __nv_bfloat16* __restrict__ Ql_g,
              const __nv_bfloat16* __restrict__ Kh_g, const __nv_bfloat16* __restrict__ Kl_g,
              const __nv_bfloat16* __restrict__ Vh_g, const __nv_bfloat16* __restrict__ Vl_g,
              __nv_bfloat16* __restrict__ AOh, __nv_bfloat16* __restrict__ AOl)
{
    extern __shared__ __nv_bfloat16 asmem[];

    const int tid  = threadIdx.x;
    const int wid  = tid >> 5;
    const int lane = tid & 31;
    const int lq   = lane >> 2;
    const int c2   = (lane & 3) << 1;

    const int qt = (int)gridDim.x - 1 - (int)blockIdx.x;
    const int q0 = qt * 128;
    const int h  = blockIdx.y;
    const int b  = blockIdx.z;
    const size_t base = (size_t)(b * H_ + h) * S_ * DH_;
    const int wrow = wid * 16;

    const uint32_t sbase = smem_u32(asmem);
    const int kn_off = (lane & 7) + ((lane & 16) ? 8 : 0);
    const int kk_off = (lane & 8);
    const int vr_off = lane & 15;
    const int vc_off = (lane & 16) ? 8 : 0;

    auto issue = [&](int k0, int s) {
#pragma unroll
        for (int it = 0; it < 2; ++it) {
            const int idx = tid + it * 256;
            const int row = idx >> 3;
            const int c16 = idx & 7;
            const size_t go = base + (size_t)(k0 + row) * DH_ + c16 * 8;
            const uint32_t so = (uint32_t)(row * ARS * 2 + c16 * 16);
#pragma unroll
            for (int a = 0; a < 4; ++a) {
                const __nv_bfloat16* g =
                    (a == 0) ? Kh_g + go : (a == 1) ? Kl_g + go :
                    (a == 2) ? Vh_g + go : Vl_g + go;
                cp16(sbase + (uint32_t)((s * 4 + a) * ATT_TILE_BF16 * 2) + so, g);
            }
        }
        cp_commit();
    };

    // Q fragment base pointers (frags loaded per tile; L1-resident)
    const __nv_bfloat16* qhp = Qh_g + base + (size_t)(q0 + wrow + lq) * DH_;
    const __nv_bfloat16* qlp = Ql_g + base + (size_t)(q0 + wrow + lq) * DH_;

    float oacc[8][4];
#pragma unroll
    for (int nt = 0; nt < 8; ++nt)
#pragma unroll
        for (int r = 0; r < 4; ++r) oacc[nt][r] = 0.0f;

    float m0 = -1e30f, m1 = -1e30f, l0 = 0.0f, l1 = 0.0f;

    const int r0g = q0 + wrow + lq;
    const int r1g = r0g + 8;
    const int rmaxWarp = q0 + wrow + 15;
    const int ntiles = q0 / 64 + 2;

    issue(0, 0);
    issue(64, 1);

    for (int t = 0; t < ntiles; ++t) {
        const int s  = t % 3;
        const int k0 = t * 64;
        if (t + 1 < ntiles) cp_wait<1>();
        else                cp_wait<0>();
        __syncthreads();
        if (t + 2 < ntiles) issue((t + 2) * 64, (t + 2) % 3);

        if (k0 <= rmaxWarp) {
            const uint32_t khu = sbase + (uint32_t)((s * 4 + 0) * ATT_TILE_BF16 * 2);
            const uint32_t klu = sbase + (uint32_t)((s * 4 + 1) * ATT_TILE_BF16 * 2);
            const uint32_t vhu = sbase + (uint32_t)((s * 4 + 2) * ATT_TILE_BF16 * 2);
            const uint32_t vlu = sbase + (uint32_t)((s * 4 + 3) * ATT_TILE_BF16 * 2);

            float sc[8][4];
#pragma unroll
            for (int nt = 0; nt < 8; ++nt)
#pragma unroll
                for (int r = 0; r < 4; ++r) sc[nt][r] = 0.0f;

#pragma unroll
            for (int kt = 0; kt < 4; ++kt) {
                // Q frags for this kt (8+8 b32 from L1)
                uint32_t qh[4], ql[4];
                {
                    const int c = kt * 16 + c2;
                    qh[0] = *(const uint32_t*)(qhp + c);
                    qh[1] = *(const uint32_t*)(qhp + 8 * DH_ + c);
                    qh[2] = *(const uint32_t*)(qhp + c + 8);
                    qh[3] = *(const uint32_t*)(qhp + 8 * DH_ + c + 8);
                    ql[0] = *(const uint32_t*)(qlp + c);
                    ql[1] = *(const uint32_t*)(qlp + 8 * DH_ + c);
                    ql[2] = *(const uint32_t*)(qlp + c + 8);
                    ql[3] = *(const uint32_t*)(qlp + 8 * DH_ + c + 8);
                }
#pragma unroll
                for (int nt2 = 0; nt2 < 4; ++nt2) {
                    const uint32_t boff =
                        (uint32_t)(((nt2 * 16 + kn_off) * ARS + kt * 16 + kk_off) * 2);
                    uint32_t kh4[4], kl4[4];
                    ldsm4(kh4, khu + boff);
                    ldsm4(kl4, klu + boff);
                    const int nt = nt2 * 2;
                    mma16816(sc[nt],     qh, kh4);
                    mma16816(sc[nt],     qh, kl4);
                    mma16816(sc[nt],     ql, kh4);
                    mma16816(sc[nt + 1], qh, kh4 + 2);
                    mma16816(sc[nt + 1], qh, kl4 + 2);
                    mma16816(sc[nt + 1], ql, kh4 + 2);
                }
            }

            // ---- causal mask (scores already scaled via Q) ----
            const bool needMask = (k0 + 64 > q0 + wrow);
            if (needMask) {
#pragma unroll
                for (int nt = 0; nt < 8; ++nt) {
                    const int c0g = k0 + nt * 8 + c2;
                    if (c0g     > r0g) sc[nt][0] = -1e30f;
                    if (c0g + 1 > r0g) sc[nt][1] = -1e30f;
                    if (c0g     > r1g) sc[nt][2] = -1e30f;
                    if (c0g + 1 > r1g) sc[nt][3] = -1e30f;
                }
            }

            // ---- online softmax ----
            float mx0 = -1e30f, mx1 = -1e30f;
#pragma unroll
            for (int nt = 0; nt < 8; ++nt) {
                mx0 = fmaxf(mx0, fmaxf(sc[nt][0], sc[nt][1]));
                mx1 = fmaxf(mx1, fmaxf(sc[nt][2], sc[nt][3]));
            }
            mx0 = fmaxf(mx0, __shfl_xor_sync(0xffffffffu, mx0, 1));
            mx0 = fmaxf(mx0, __shfl_xor_sync(0xffffffffu, mx0, 2));
            mx1 = fmaxf(mx1, __shfl_xor_sync(0xffffffffu, mx1, 1));
            mx1 = fmaxf(mx1, __shfl_xor_sync(0xffffffffu, mx1, 2));

            const float mn0 = fmaxf(m0, mx0);
            const float mn1 = fmaxf(m1, mx1);
            const float corr0 = __expf(m0 - mn0);
            const float corr1 = __expf(m1 - mn1);
            m0 = mn0; m1 = mn1;

            float rs0 = 0.0f, rs1 = 0.0f;
#pragma unroll
            for (int nt = 0; nt < 8; ++nt) {
                float p0 = __expf(sc[nt][0] - mn0);
                float p1 = __expf(sc[nt][1] - mn0);
                float p2 = __expf(sc[nt][2] - mn1);
                float p3 = __expf(sc[nt][3] - mn1);
                sc[nt][0] = p0; sc[nt][1] = p1; sc[nt][2] = p2; sc[nt][3] = p3;
                rs0 += p0 + p1;
                rs1 += p2 + p3;
            }
            rs0 += __shfl_xor_sync(0xffffffffu, rs0, 1);
            rs0 += __shfl_xor_sync(0xffffffffu, rs0, 2);
            rs1 += __shfl_xor_sync(0xffffffffu, rs1, 1);
            rs1 += __shfl_xor_sync(0xffffffffu, rs1, 2);
            l0 = l0 * corr0 + rs0;
            l1 = l1 * corr1 + rs1;

#pragma unroll
            for (int nt = 0; nt < 8; ++nt) {
                oacc[nt][0] *= corr0; oacc[nt][1] *= corr0;
                oacc[nt][2] *= corr1; oacc[nt][3] *= corr1;
            }

            // ---- pack P (split hi/lo) ----
            uint32_t ph[4][4], pl[4][4];
#pragma unroll
            for (int kt = 0; kt < 4; ++kt) {
                const int t0 = 2 * kt, t1 = 2 * kt + 1;
                split2(sc[t0][0], sc[t0][1], ph[kt][0], pl[kt][0]);
                split2(sc[t0][2], sc[t0][3], ph[kt][1], pl[kt][1]);
                split2(sc[t1][0], sc[t1][1], ph[kt][2], pl[kt][2]);
                split2(sc[t1][2], sc[t1][3], ph[kt][3], pl[kt][3]);
            }

            // ---- O += P V ----
#pragma unroll
            for (int kt = 0; kt < 4; ++kt) {
#pragma unroll
                for (int nt2 = 0; nt2 < 4; ++nt2) {
                    const uint32_t boff =
                        (uint32_t)(((kt * 16 + vr_off) * ARS + nt2 * 16 + vc_off) * 2);
                    uint32_t vh4[4], vl4[4];
                    ldsm4t(vh4, vhu + boff);
                    ldsm4t(vl4, vlu + boff);
                    const int nt = nt2 * 2;
                    mma16816(oacc[nt],     ph[kt], vh4);
                    mma16816(oacc[nt],     ph[kt], vl4);
                    mma16816(oacc[nt],     pl[kt], vh4);
                    mma16816(oacc[nt + 1], ph[kt], vh4 + 2);
                    mma16816(oacc[nt + 1], ph[kt], vl4 + 2);
                    mma16816(oacc[nt + 1], pl[kt], vh4 + 2);
                }
            }
        }
    }

    const float inv0 = 1.0f / l0;
    const float inv1 = 1.0f / l1;
#pragma unroll
    for (int nt = 0; nt < 8; ++nt) {
        const int d = h * DH_ + nt * 8 + c2;
        uint32_t hh, ll;
        split2(oacc[nt][0] * inv0, oacc[nt][1] * inv0, hh, ll);
        *(uint32_t*)&AOh[(size_t)(b * S_ + r0g) * D_ + d] = hh;
        *(uint32_t*)&AOl[(size_t)(b * S_ + r0g) * D_ + d] = ll;
        split2(oacc[nt][2] * inv1, oacc[nt][3] * inv1, hh, ll);
        *(uint32_t*)&AOh[(size_t)(b * S_ + r1g) * D_ + d] = hh;
        *(uint32_t*)&AOl[(size_t)(b * S_ + r1g) * D_ + d] = ll;
    }
}

// ---------------------------------------------------------------------------
// Launch
// ---------------------------------------------------------------------------
extern "C" void kernel_launch(void* const* d_in, const int* in_sizes, int n_in,
                              void* d_out, int out_size)
{
    const float* x  = (const float*)d_in[0];
    const float* w0 = (const float*)d_in[1];
    const float* w1 = (const float*)d_in[2];
    const float* w2 = (const float*)d_in[3];
    const float* w3 = (const float*)d_in[4];
    float* out = (float*)d_out;

    void *pxh, *pxl, *pwh, *pwl, *pqkvh, *pqkvl, *paoh, *paol;
    cudaGetSymbolAddress(&pxh, g_xh);     cudaGetSymbolAddress(&pxl, g_xl);
    cudaGetSymbolAddress(&pwh, g_wh);     cudaGetSymbolAddress(&pwl, g_wl);
    cudaGetSymbolAddress(&pqkvh, g_qkvh); cudaGetSymbolAddress(&pqkvl, g_qkvl);
    cudaGetSymbolAddress(&paoh, g_aoh);   cudaGetSymbolAddress(&paol, g_aol);

    __nv_bfloat16* xh = (__nv_bfloat16*)pxh;     __nv_bfloat16* xl = (__nv_bfloat16*)pxl;
    __nv_bfloat16* wh = (__nv_bfloat16*)pwh;     __nv_bfloat16* wl = (__nv_bfloat16*)pwl;
    __nv_bfloat16* qkvh = (__nv_bfloat16*)pqkvh; __nv_bfloat16* qkvl = (__nv_bfloat16*)pqkvl;
    __nv_bfloat16* aoh = (__nv_bfloat16*)paoh;   __nv_bfloat16* aol = (__nv_bfloat16*)paol;

    {
        const int ntot = M_ * D_ / 4 + 4 * (D_ * D_ / 4);
        split_all<<<(ntot + 255) / 256, 256>>>(
            (const float4*)x, (const float4*)w0, (const float4*)w1,
            (const float4*)w2, (const float4*)w3,
            (uint2*)xh, (uint2*)xl, (uint2*)wh, (uint2*)wl);
    }

    cudaFuncSetAttribute(gemm_bf16<0>, cudaFuncAttributeMaxDynamicSharedMemorySize, GEMM_SMEM);
    cudaFuncSetAttribute(gemm_bf16<1>, cudaFuncAttributeMaxDynamicSharedMemorySize, GEMM_SMEM);
    cudaFuncSetAttribute(attn_mma,     cudaFuncAttributeMaxDynamicSharedMemorySize, ATT_SMEM);

    // Fused QKV: grid.x = 3 weights x 8 n-tiles
    dim3 qkv_grid(24, M_ / 128);
    gemm_bf16<0><<<qkv_grid, 256, GEMM_SMEM>>>(xh, xl, wh, wl, qkvh, qkvl, nullptr);

    dim3 attn_grid(S_ / 128, H_, B_);
    attn_mma<<<attn_grid, 256, ATT_SMEM>>>(
        qkvh + 0 * (size_t)M_ * D_, qkvl + 0 * (size_t)M_ * D_,
        qkvh + 1 * (size_t)M_ * D_, qkvl + 1 * (size_t)M_ * D_,
        qkvh + 2 * (size_t)M_ * D_, qkvl + 2 * (size_t)M_ * D_,
        aoh, aol);

    dim3 gemm_grid(D_ / 128, M_ / 128);
    gemm_bf16<1><<<gemm_grid, 256, GEMM_SMEM>>>(
        aoh, aol, wh + 3 * (size_t)D_ * D_, wl + 3 * (size_t)D_ * D_,
        nullptr, nullptr, out);
}

// round 13
// speedup vs baseline: 1.2859x; 1.2859x over previous
#include <cuda_runtime.h>
#include <cuda_bf16.h>
#include <cuda_fp16.h>
#include <cstdint>
#include <cstddef>

// ---------------------------------------------------------------------------
// Problem constants
// ---------------------------------------------------------------------------
constexpr int B_  = 2;
constexpr int S_  = 2048;
constexpr int D_  = 1024;
constexpr int H_  = 16;
constexpr int DH_ = 64;
constexpr int M_  = B_ * S_;   // 4096

// ---------------------------------------------------------------------------
// Scratch
//   x, attention-output: fp16 hi/lo pairs (GEMM A operands, 2-term split)
//   weights: single fp16 (GEMM B operands)
//   Q/K/V: bf16 hi/lo pairs (attention operands, 3-term split — unchanged)
// ---------------------------------------------------------------------------
__device__ __align__(256) __half g_xh[(size_t)M_ * D_], g_xl[(size_t)M_ * D_];
__device__ __align__(256) __half g_w[4][(size_t)D_ * D_];
__device__ __align__(256) __nv_bfloat16 g_qkvh[3][(size_t)M_ * D_], g_qkvl[3][(size_t)M_ * D_];
__device__ __align__(256) __half g_aoh[(size_t)M_ * D_], g_aol[(size_t)M_ * D_];

// ---------------------------------------------------------------------------
// Helpers
// ---------------------------------------------------------------------------
__device__ __forceinline__ void mma_bf16(float* c, const uint32_t* a, const uint32_t* b) {
    asm volatile(
        "mma.sync.aligned.m16n8k16.row.col.f32.bf16.bf16.f32 "
        "{%0,%1,%2,%3}, {%4,%5,%6,%7}, {%8,%9}, {%0,%1,%2,%3};"
        : "+f"(c[0]), "+f"(c[1]), "+f"(c[2]), "+f"(c[3])
        : "r"(a[0]), "r"(a[1]), "r"(a[2]), "r"(a[3]), "r"(b[0]), "r"(b[1]));
}
__device__ __forceinline__ void mma_fp16(float* c, const uint32_t* a, const uint32_t* b) {
    asm volatile(
        "mma.sync.aligned.m16n8k16.row.col.f32.f16.f16.f32 "
        "{%0,%1,%2,%3}, {%4,%5,%6,%7}, {%8,%9}, {%0,%1,%2,%3};"
        : "+f"(c[0]), "+f"(c[1]), "+f"(c[2]), "+f"(c[3])
        : "r"(a[0]), "r"(a[1]), "r"(a[2]), "r"(a[3]), "r"(b[0]), "r"(b[1]));
}

// bf16 hi/lo split (attention path)
__device__ __forceinline__ void split2(float x, float y, uint32_t& hi, uint32_t& lo) {
    __nv_bfloat162 h = __floats2bfloat162_rn(x, y);
    float rx = x - __bfloat162float(h.x);
    float ry = y - __bfloat162float(h.y);
    __nv_bfloat162 l = __floats2bfloat162_rn(rx, ry);
    hi = *reinterpret_cast<uint32_t*>(&h);
    lo = *reinterpret_cast<uint32_t*>(&l);
}
// fp16 hi/lo split (GEMM A-operand path)
__device__ __forceinline__ void split2h(float x, float y, uint32_t& hi, uint32_t& lo) {
    __half2 h = __floats2half2_rn(x, y);
    float rx = x - __half2float(h.x);
    float ry = y - __half2float(h.y);
    __half2 l = __floats2half2_rn(rx, ry);
    hi = *reinterpret_cast<uint32_t*>(&h);
    lo = *reinterpret_cast<uint32_t*>(&l);
}

__device__ __forceinline__ uint32_t smem_u32(const void* p) {
    uint32_t a;
    asm("{ .reg .u64 t; cvta.to.shared.u64 t, %1; cvt.u32.u64 %0, t; }" : "=r"(a) : "l"(p));
    return a;
}

__device__ __forceinline__ void ldsm4(uint32_t* r, uint32_t addr) {
    asm volatile("ldmatrix.sync.aligned.m8n8.x4.shared.b16 {%0,%1,%2,%3}, [%4];"
        : "=r"(r[0]), "=r"(r[1]), "=r"(r[2]), "=r"(r[3]) : "r"(addr));
}
__device__ __forceinline__ void ldsm4t(uint32_t* r, uint32_t addr) {
    asm volatile("ldmatrix.sync.aligned.m8n8.x4.trans.shared.b16 {%0,%1,%2,%3}, [%4];"
        : "=r"(r[0]), "=r"(r[1]), "=r"(r[2]), "=r"(r[3]) : "r"(addr));
}

__device__ __forceinline__ void cp16(uint32_t saddr, const void* g) {
    asm volatile("cp.async.cg.shared.global [%0], [%1], 16;" :: "r"(saddr), "l"(g));
}
__device__ __forceinline__ void cp_commit() { asm volatile("cp.async.commit_group;"); }
template <int N> __device__ __forceinline__ void cp_wait() {
    asm volatile("cp.async.wait_group %0;" :: "n"(N));
}

// ---------------------------------------------------------------------------
// Fused splitter: x -> fp16 hi/lo; weights -> single fp16.
// ---------------------------------------------------------------------------
__global__ void split_all(const float4* __restrict__ x,
                          const float4* __restrict__ w0, const float4* __restrict__ w1,
                          const float4* __restrict__ w2, const float4* __restrict__ w3,
                          uint2* __restrict__ xh, uint2* __restrict__ xl,
                          uint2* __restrict__ wh)
{
    const int i = blockIdx.x * blockDim.x + threadIdx.x;
    constexpr int NX = M_ * D_ / 4;
    constexpr int NW = D_ * D_ / 4;

    if (i < NX) {
        float4 f = x[i];
        uint32_t h01, l01, h23, l23;
        split2h(f.x, f.y, h01, l01);
        split2h(f.z, f.w, h23, l23);
        xh[i] = make_uint2(h01, h23);
        xl[i] = make_uint2(l01, l23);
    } else if (i < NX + 4 * NW) {
        const int j = i - NX;
        const int wsel = j / NW;
        const int k = j - wsel * NW;
        const float4* ws[4] = {w0, w1, w2, w3};
        float4 f = ws[wsel][k];
        __half2 h01 = __floats2half2_rn(f.x, f.y);
        __half2 h23 = __floats2half2_rn(f.z, f.w);
        wh[(size_t)wsel * NW + k] =
            make_uint2(*reinterpret_cast<uint32_t*>(&h01),
                       *reinterpret_cast<uint32_t*>(&h23));
    }
}

// ---------------------------------------------------------------------------
// GEMM fp16 2-term: out = (Ah+Al) * Wh^T.  A split fp16 hi/lo; W single fp16.
// R8 structure: tile 128x128x32, 8 warps, warp 64x32, cp.async 2-stage,
// one barrier per k-iter, 2 CTAs/SM. 64 MMAs per k-tile per warp (was 96).
// smem/stage: [Ah][Al][Bh] each 128*40 fp16; 2 stages = 61440 B.
// MODE 0: fused QKV (blockIdx.x>>3 selects weight), scatter bf16 hi/lo.
// MODE 1: single weight, fp32 row-major output.
// ---------------------------------------------------------------------------
constexpr int RS = 40;
constexpr int GEMM_TILE = 128 * RS;                  // elems per array per stage
constexpr int GSTAGE = 3 * GEMM_TILE;
constexpr int GEMM_SMEM = 2 * GSTAGE * 2;            // 61440 B

template <int MODE>
__global__ __launch_bounds__(256, 2)
void gemm_fp16(const __half* __restrict__ Ah_g, const __half* __restrict__ Al_g,
               const __half* __restrict__ Wh0,
               __nv_bfloat16* __restrict__ Oh0, __nv_bfloat16* __restrict__ Ol0,
               float* __restrict__ Of)
{
    extern __shared__ __half smem[];

    const int tid  = threadIdx.x;
    const int wid  = tid >> 5;
    const int lane = tid & 31;
    const int wm   = wid >> 2;
    const int wn   = wid & 3;
    const int lq   = lane >> 2;
    const int lr   = (lane & 3) << 1;

    int wsel, bn;
    if (MODE == 0) { wsel = blockIdx.x >> 3; bn = (blockIdx.x & 7) * 128; }
    else           { wsel = 0;               bn = blockIdx.x * 128; }
    const int bm = blockIdx.y * 128;

    const __half* Bh_g = Wh0 + (size_t)wsel * D_ * D_;

    const uint32_t sbase = smem_u32(smem);

    // copy: 3 arrays x 512 cp16 = 1536; 6 per thread
    auto issue = [&](int k0, int s) {
#pragma unroll
        for (int i = 0; i < 6; ++i) {
            const int a    = i >> 1;              // 0=Ah 1=Al 2=Bh
            const int c    = (i & 1) * 256 + tid; // 0..511
            const int row  = c >> 2;
            const int c16  = c & 3;
            const size_t go = (size_t)((a < 2 ? bm : bn) + row) * D_ + k0 + c16 * 8;
            const __half* g = (a == 0) ? Ah_g + go : (a == 1) ? Al_g + go : Bh_g + go;
            const uint32_t sa = sbase + (uint32_t)(((s * 3 + a) * GEMM_TILE
                                 + row * RS) * 2 + c16 * 16);
            cp16(sa, g);
        }
        cp_commit();
    };

    float acc[4][4][4];
#pragma unroll
    for (int i = 0; i < 4; i++)
#pragma unroll
        for (int j = 0; j < 4; j++)
#pragma unroll
            for (int r = 0; r < 4; r++) acc[i][j][r] = 0.0f;

    issue(0, 0);

    for (int kt = 0; kt < 32; ++kt) {
        const int s = kt & 1;
        cp_wait<0>();
        __syncthreads();
        if (kt < 31) issue((kt + 1) * 32, s ^ 1);

        const __half* Ahs = smem + (s * 3 + 0) * GEMM_TILE;
        const __half* Als = smem + (s * 3 + 1) * GEMM_TILE;
        const __half* Bhs = smem + (s * 3 + 2) * GEMM_TILE;

#pragma unroll
        for (int ks = 0; ks < 2; ++ks) {
            const int kb = ks * 16 + lr;

            uint32_t bh[4][2];
#pragma unroll
            for (int nt = 0; nt < 4; ++nt) {
                const int n = wn * 32 + nt * 8 + lq;
                bh[nt][0] = *(const uint32_t*)&Bhs[n * RS + kb];
                bh[nt][1] = *(const uint32_t*)&Bhs[n * RS + kb + 8];
            }

#pragma unroll
            for (int mt = 0; mt < 4; ++mt) {
                const int r = wm * 64 + mt * 16 + lq;
                uint32_t ah[4], al[4];
                ah[0] = *(const uint32_t*)&Ahs[r * RS + kb];
                ah[1] = *(const uint32_t*)&Ahs[(r + 8) * RS + kb];
                ah[2] = *(const uint32_t*)&Ahs[r * RS + kb + 8];
                ah[3] = *(const uint32_t*)&Ahs[(r + 8) * RS + kb + 8];
                al[0] = *(const uint32_t*)&Als[r * RS + kb];
                al[1] = *(const uint32_t*)&Als[(r + 8) * RS + kb];
                al[2] = *(const uint32_t*)&Als[r * RS + kb + 8];
                al[3] = *(const uint32_t*)&Als[(r + 8) * RS + kb + 8];
#pragma unroll
                for (int nt = 0; nt < 4; ++nt) {
                    mma_fp16(acc[mt][nt], ah, bh[nt]);
                    mma_fp16(acc[mt][nt], al, bh[nt]);
                }
            }
        }
    }

    __nv_bfloat16* Oh = (MODE == 0) ? Oh0 + (size_t)wsel * M_ * D_ : nullptr;
    __nv_bfloat16* Ol = (MODE == 0) ? Ol0 + (size_t)wsel * M_ * D_ : nullptr;

#pragma unroll
    for (int mt = 0; mt < 4; ++mt) {
#pragma unroll
        for (int nt = 0; nt < 4; ++nt) {
            const int n  = bn + wn * 32 + nt * 8 + lr;
            const int m0 = bm + wm * 64 + mt * 16 + lq;
#pragma unroll
            for (int half = 0; half < 2; ++half) {
                const int m = m0 + half * 8;
                const float v0 = acc[mt][nt][half * 2];
                const float v1 = acc[mt][nt][half * 2 + 1];
                if (MODE == 0) {
                    const int b_ = m >> 11;
                    const int s_ = m & 2047;
                    const int h_ = n >> 6;
                    const int d_ = n & 63;
                    const size_t off = (((size_t)(b_ * H_ + h_) * S_ + s_) << 6) + d_;
                    uint32_t hh, ll;
                    split2(v0, v1, hh, ll);        // bf16 pairs for attention
                    *(uint32_t*)&Oh[off] = hh;
                    *(uint32_t*)&Ol[off] = ll;
                } else {
                    *(float2*)&Of[(size_t)m * D_ + n] = make_float2(v0, v1);
                }
            }
        }
    }
}

// ---------------------------------------------------------------------------
// Flash attention (exact Round-8 best): bf16 3-term, cp.async 3-stage K/V
// pipeline, one barrier per tile. Output now written as fp16 hi/lo pairs
// (A operand of the fp16 2-term output GEMM).
// ---------------------------------------------------------------------------
constexpr int ARS = 72;
constexpr int ATT_TILE_BF16 = 64 * ARS;
constexpr int ATT_SMEM = 3 * 4 * ATT_TILE_BF16 * 2;   // 110592 B

__global__ __launch_bounds__(256)
void attn_mma(const __nv_bfloat16* __restrict__ Qh_g, const __nv_bfloat16* __restrict__ Ql_g,
              const __nv_bfloat16* __restrict__ Kh_g, const __nv_bfloat16* __restrict__ Kl_g,
              const __nv_bfloat16* __restrict__ Vh_g, const __nv_bfloat16* __restrict__ Vl_g,
              __half* __restrict__ AOh, __half* __restrict__ AOl)
{
    extern __shared__ __nv_bfloat16 asmem[];

    const int tid  = threadIdx.x;
    const int wid  = tid >> 5;
    const int lane = tid & 31;
    const int lq   = lane >> 2;
    const int c2   = (lane & 3) << 1;

    const int qt = (int)gridDim.x - 1 - (int)blockIdx.x;
    const int q0 = qt * 128;
    const int h  = blockIdx.y;
    const int b  = blockIdx.z;
    const size_t base = (size_t)(b * H_ + h) * S_ * DH_;
    const int wrow = wid * 16;

    const uint32_t sbase = smem_u32(asmem);
    const int kn_off = (lane & 7) + ((lane & 16) ? 8 : 0);
    const int kk_off = (lane & 8);
    const int vr_off = lane & 15;
    const int vc_off = (lane & 16) ? 8 : 0;

    auto issue = [&](int k0, int s) {
#pragma unroll
        for (int it = 0; it < 2; ++it) {
            const int idx = tid + it * 256;
            const int row = idx >> 3;
            const int c16 = idx & 7;
            const size_t go = base + (size_t)(k0 + row) * DH_ + c16 * 8;
            const uint32_t so = (uint32_t)(row * ARS * 2 + c16 * 16);
#pragma unroll
            for (int a = 0; a < 4; ++a) {
                const __nv_bfloat16* g =
                    (a == 0) ? Kh_g + go : (a == 1) ? Kl_g + go :
                    (a == 2) ? Vh_g + go : Vl_g + go;
                cp16(sbase + (uint32_t)((s * 4 + a) * ATT_TILE_BF16 * 2) + so, g);
            }
        }
        cp_commit();
    };

    uint32_t qh[4][4], ql[4][4];
    {
        const __nv_bfloat16* qhp = Qh_g + base + (size_t)(q0 + wrow + lq) * DH_;
        const __nv_bfloat16* qlp = Ql_g + base + (size_t)(q0 + wrow + lq) * DH_;
#pragma unroll
        for (int kt = 0; kt < 4; ++kt) {
            const int c = kt * 16 + c2;
            qh[kt][0] = *(const uint32_t*)(qhp + c);
            qh[kt][1] = *(const uint32_t*)(qhp + 8 * DH_ + c);
            qh[kt][2] = *(const uint32_t*)(qhp + c + 8);
            qh[kt][3] = *(const uint32_t*)(qhp + 8 * DH_ + c + 8);
            ql[kt][0] = *(const uint32_t*)(qlp + c);
            ql[kt][1] = *(const uint32_t*)(qlp + 8 * DH_ + c);
            ql[kt][2] = *(const uint32_t*)(qlp + c + 8);
            ql[kt][3] = *(const uint32_t*)(qlp + 8 * DH_ + c + 8);
        }
    }

    float oacc[8][4];
#pragma unroll
    for (int nt = 0; nt < 8; ++nt)
#pragma unroll
        for (int r = 0; r < 4; ++r) oacc[nt][r] = 0.0f;

    float m0 = -1e30f, m1 = -1e30f, l0 = 0.0f, l1 = 0.0f;

    constexpr float scale = 0.125f;
    const int r0g = q0 + wrow + lq;
    const int r1g = r0g + 8;
    const int rmaxWarp = q0 + wrow + 15;
    const int ntiles = q0 / 64 + 2;

    issue(0, 0);
    issue(64, 1);

    for (int t = 0; t < ntiles; ++t) {
        const int s  = t % 3;
        const int k0 = t * 64;
        if (t + 1 < ntiles) cp_wait<1>();
        else                cp_wait<0>();
        __syncthreads();
        if (t + 2 < ntiles) issue((t + 2) * 64, (t + 2) % 3);

        if (k0 <= rmaxWarp) {
            const uint32_t khu = sbase + (uint32_t)((s * 4 + 0) * ATT_TILE_BF16 * 2);
            const uint32_t klu = sbase + (uint32_t)((s * 4 + 1) * ATT_TILE_BF16 * 2);
            const uint32_t vhu = sbase + (uint32_t)((s * 4 + 2) * ATT_TILE_BF16 * 2);
            const uint32_t vlu = sbase + (uint32_t)((s * 4 + 3) * ATT_TILE_BF16 * 2);

            float sc[8][4];
#pragma unroll
            for (int nt = 0; nt < 8; ++nt)
#pragma unroll
                for (int r = 0; r < 4; ++r) sc[nt][r] = 0.0f;

#pragma unroll
            for (int kt = 0; kt < 4; ++kt) {
#pragma unroll
                for (int nt2 = 0; nt2 < 4; ++nt2) {
                    const uint32_t boff =
                        (uint32_t)(((nt2 * 16 + kn_off) * ARS + kt * 16 + kk_off) * 2);
                    uint32_t kh4[4], kl4[4];
                    ldsm4(kh4, khu + boff);
                    ldsm4(kl4, klu + boff);
                    const int nt = nt2 * 2;
                    mma_bf16(sc[nt],     qh[kt], kh4);
                    mma_bf16(sc[nt],     qh[kt], kl4);
                    mma_bf16(sc[nt],     ql[kt], kh4);
                    mma_bf16(sc[nt + 1], qh[kt], kh4 + 2);
                    mma_bf16(sc[nt + 1], qh[kt], kl4 + 2);
                    mma_bf16(sc[nt + 1], ql[kt], kh4 + 2);
                }
            }

            const bool needMask = (k0 + 64 > q0 + wrow);
#pragma unroll
            for (int nt = 0; nt < 8; ++nt) {
                const int c0g = k0 + nt * 8 + c2;
                sc[nt][0] *= scale; sc[nt][1] *= scale;
                sc[nt][2] *= scale; sc[nt][3] *= scale;
                if (needMask) {
                    if (c0g     > r0g) sc[nt][0] = -1e30f;
                    if (c0g + 1 > r0g) sc[nt][1] = -1e30f;
                    if (c0g     > r1g) sc[nt][2] = -1e30f;
                    if (c0g + 1 > r1g) sc[nt][3] = -1e30f;
                }
            }

            float mx0 = -1e30f, mx1 = -1e30f;
#pragma unroll
            for (int nt = 0; nt < 8; ++nt) {
                mx0 = fmaxf(mx0, fmaxf(sc[nt][0], sc[nt][1]));
                mx1 = fmaxf(mx1, fmaxf(sc[nt][2], sc[nt][3]));
            }
            mx0 = fmaxf(mx0, __shfl_xor_sync(0xffffffffu, mx0, 1));
            mx0 = fmaxf(mx0, __shfl_xor_sync(0xffffffffu, mx0, 2));
            mx1 = fmaxf(mx1, __shfl_xor_sync(0xffffffffu, mx1, 1));
            mx1 = fmaxf(mx1, __shfl_xor_sync(0xffffffffu, mx1, 2));

            const float mn0 = fmaxf(m0, mx0);
            const float mn1 = fmaxf(m1, mx1);
            const float corr0 = __expf(m0 - mn0);
            const float corr1 = __expf(m1 - mn1);
            m0 = mn0; m1 = mn1;

            float rs0 = 0.0f, rs1 = 0.0f;
#pragma unroll
            for (int nt = 0; nt < 8; ++nt) {
                float p0 = __expf(sc[nt][0] - mn0);
                float p1 = __expf(sc[nt][1] - mn0);
                float p2 = __expf(sc[nt][2] - mn1);
                float p3 = __expf(sc[nt][3] - mn1);
                sc[nt][0] = p0; sc[nt][1] = p1; sc[nt][2] = p2; sc[nt][3] = p3;
                rs0 += p0 + p1;
                rs1 += p2 + p3;
            }
            rs0 += __shfl_xor_sync(0xffffffffu, rs0, 1);
            rs0 += __shfl_xor_sync(0xffffffffu, rs0, 2);
            rs1 += __shfl_xor_sync(0xffffffffu, rs1, 1);
            rs1 += __shfl_xor_sync(0xffffffffu, rs1, 2);
            l0 = l0 * corr0 + rs0;
            l1 = l1 * corr1 + rs1;

#pragma unroll
            for (int nt = 0; nt < 8; ++nt) {
                oacc[nt][0] *= corr0; oacc[nt][1] *= corr0;
                oacc[nt][2] *= corr1; oacc[nt][3] *= corr1;
            }

            uint32_t ph[4][4], pl[4][4];
#pragma unroll
            for (int kt = 0; kt < 4; ++kt) {
                const int t0 = 2 * kt, t1 = 2 * kt + 1;
                split2(sc[t0][0], sc[t0][1], ph[kt][0], pl[kt][0]);
                split2(sc[t0][2], sc[t0][3], ph[kt][1], pl[kt][1]);
                split2(sc[t1][0], sc[t1][1], ph[kt][2], pl[kt][2]);
                split2(sc[t1][2], sc[t1][3], ph[kt][3], pl[kt][3]);
            }

#pragma unroll
            for (int kt = 0; kt < 4; ++kt) {
#pragma unroll
                for (int nt2 = 0; nt2 < 4; ++nt2) {
                    const uint32_t boff =
                        (uint32_t)(((kt * 16 + vr_off) * ARS + nt2 * 16 + vc_off) * 2);
                    uint32_t vh4[4], vl4[4];
                    ldsm4t(vh4, vhu + boff);
                    ldsm4t(vl4, vlu + boff);
                    const int nt = nt2 * 2;
                    mma_bf16(oacc[nt],     ph[kt], vh4);
                    mma_bf16(oacc[nt],     ph[kt], vl4);
                    mma_bf16(oacc[nt],     pl[kt], vh4);
                    mma_bf16(oacc[nt + 1], ph[kt], vh4 + 2);
                    mma_bf16(oacc[nt + 1], ph[kt], vl4 + 2);
                    mma_bf16(oacc[nt + 1], pl[kt], vh4 + 2);
                }
            }
        }
    }

    // epilogue: normalize, write fp16 hi/lo pairs for the output GEMM
    const float inv0 = 1.0f / l0;
    const float inv1 = 1.0f / l1;
#pragma unroll
    for (int nt = 0; nt < 8; ++nt) {
        const int d = h * DH_ + nt * 8 + c2;
        uint32_t hh, ll;
        split2h(oacc[nt][0] * inv0, oacc[nt][1] * inv0, hh, ll);
        *(uint32_t*)&AOh[(size_t)(b * S_ + r0g) * D_ + d] = hh;
        *(uint32_t*)&AOl[(size_t)(b * S_ + r0g) * D_ + d] = ll;
        split2h(oacc[nt][2] * inv1, oacc[nt][3] * inv1, hh, ll);
        *(uint32_t*)&AOh[(size_t)(b * S_ + r1g) * D_ + d] = hh;
        *(uint32_t*)&AOl[(size_t)(b * S_ + r1g) * D_ + d] = ll;
    }
}

// ---------------------------------------------------------------------------
// Launch
// ---------------------------------------------------------------------------
extern "C" void kernel_launch(void* const* d_in, const int* in_sizes, int n_in,
                              void* d_out, int out_size)
{
    const float* x  = (const float*)d_in[0];
    const float* w0 = (const float*)d_in[1];
    const float* w1 = (const float*)d_in[2];
    const float* w2 = (const float*)d_in[3];
    const float* w3 = (const float*)d_in[4];
    float* out = (float*)d_out;

    void *pxh, *pxl, *pw, *pqkvh, *pqkvl, *paoh, *paol;
    cudaGetSymbolAddress(&pxh, g_xh);     cudaGetSymbolAddress(&pxl, g_xl);
    cudaGetSymbolAddress(&pw, g_w);
    cudaGetSymbolAddress(&pqkvh, g_qkvh); cudaGetSymbolAddress(&pqkvl, g_qkvl);
    cudaGetSymbolAddress(&paoh, g_aoh);   cudaGetSymbolAddress(&paol, g_aol);

    __half* xh = (__half*)pxh;   __half* xl = (__half*)pxl;
    __half* wh = (__half*)pw;
    __nv_bfloat16* qkvh = (__nv_bfloat16*)pqkvh;
    __nv_bfloat16* qkvl = (__nv_bfloat16*)pqkvl;
    __half* aoh = (__half*)paoh; __half* aol = (__half*)paol;

    {
        const int ntot = M_ * D_ / 4 + 4 * (D_ * D_ / 4);
        split_all<<<(ntot + 255) / 256, 256>>>(
            (const float4*)x, (const float4*)w0, (const float4*)w1,
            (const float4*)w2, (const float4*)w3,
            (uint2*)xh, (uint2*)xl, (uint2*)wh);
    }

    cudaFuncSetAttribute(gemm_fp16<0>, cudaFuncAttributeMaxDynamicSharedMemorySize, GEMM_SMEM);
    cudaFuncSetAttribute(gemm_fp16<1>, cudaFuncAttributeMaxDynamicSharedMemorySize, GEMM_SMEM);
    cudaFuncSetAttribute(attn_mma,     cudaFuncAttributeMaxDynamicSharedMemorySize, ATT_SMEM);

    // Fused QKV: grid.x = 3 weights x 8 n-tiles
    dim3 qkv_grid(24, M_ / 128);
    gemm_fp16<0><<<qkv_grid, 256, GEMM_SMEM>>>(xh, xl, wh, qkvh, qkvl, nullptr);

    dim3 attn_grid(S_ / 128, H_, B_);
    attn_mma<<<attn_grid, 256, ATT_SMEM>>>(
        qkvh + 0 * (size_t)M_ * D_, qkvl + 0 * (size_t)M_ * D_,
        qkvh + 1 * (size_t)M_ * D_, qkvl + 1 * (size_t)M_ * D_,
        qkvh + 2 * (size_t)M_ * D_, qkvl + 2 * (size_t)M_ * D_,
        aoh, aol);

    dim3 gemm_grid(D_ / 128, M_ / 128);
    gemm_fp16<1><<<gemm_grid, 256, GEMM_SMEM>>>(
        aoh, aol, wh + 3 * (size_t)D_ * D_, nullptr, nullptr, out);
}

// round 15
// speedup vs baseline: 1.4876x; 1.1568x over previous
#include <cuda_runtime.h>
#include <cuda_bf16.h>
#include <cuda_fp16.h>
#include <cstdint>
#include <cstddef>

// ---------------------------------------------------------------------------
// Problem constants
// ---------------------------------------------------------------------------
constexpr int B_  = 2;
constexpr int S_  = 2048;
constexpr int D_  = 1024;
constexpr int H_  = 16;
constexpr int DH_ = 64;
constexpr int M_  = B_ * S_;   // 4096

// ---------------------------------------------------------------------------
// Scratch (all fp16)
//   x, attention-output: fp16 hi/lo pairs (GEMM A operands)
//   weights: single fp16
//   Q: fp16 hi/lo pair; K, V: single fp16
// ---------------------------------------------------------------------------
__device__ __align__(256) __half g_xh[(size_t)M_ * D_], g_xl[(size_t)M_ * D_];
__device__ __align__(256) __half g_w[4][(size_t)D_ * D_];
__device__ __align__(256) __half g_qh[(size_t)M_ * D_], g_ql[(size_t)M_ * D_];
__device__ __align__(256) __half g_kv[2][(size_t)M_ * D_];     // [0]=K, [1]=V
__device__ __align__(256) __half g_aoh[(size_t)M_ * D_], g_aol[(size_t)M_ * D_];

// ---------------------------------------------------------------------------
// Helpers
// ---------------------------------------------------------------------------
__device__ __forceinline__ void mma_fp16(float* c, const uint32_t* a, const uint32_t* b) {
    asm volatile(
        "mma.sync.aligned.m16n8k16.row.col.f32.f16.f16.f32 "
        "{%0,%1,%2,%3}, {%4,%5,%6,%7}, {%8,%9}, {%0,%1,%2,%3};"
        : "+f"(c[0]), "+f"(c[1]), "+f"(c[2]), "+f"(c[3])
        : "r"(a[0]), "r"(a[1]), "r"(a[2]), "r"(a[3]), "r"(b[0]), "r"(b[1]));
}

// fp16 hi/lo split
__device__ __forceinline__ void split2h(float x, float y, uint32_t& hi, uint32_t& lo) {
    __half2 h = __floats2half2_rn(x, y);
    float rx = x - __half2float(h.x);
    float ry = y - __half2float(h.y);
    __half2 l = __floats2half2_rn(rx, ry);
    hi = *reinterpret_cast<uint32_t*>(&h);
    lo = *reinterpret_cast<uint32_t*>(&l);
}

__device__ __forceinline__ uint32_t smem_u32(const void* p) {
    uint32_t a;
    asm("{ .reg .u64 t; cvta.to.shared.u64 t, %1; cvt.u32.u64 %0, t; }" : "=r"(a) : "l"(p));
    return a;
}

__device__ __forceinline__ void ldsm4(uint32_t* r, uint32_t addr) {
    asm volatile("ldmatrix.sync.aligned.m8n8.x4.shared.b16 {%0,%1,%2,%3}, [%4];"
        : "=r"(r[0]), "=r"(r[1]), "=r"(r[2]), "=r"(r[3]) : "r"(addr));
}
__device__ __forceinline__ void ldsm4t(uint32_t* r, uint32_t addr) {
    asm volatile("ldmatrix.sync.aligned.m8n8.x4.trans.shared.b16 {%0,%1,%2,%3}, [%4];"
        : "=r"(r[0]), "=r"(r[1]), "=r"(r[2]), "=r"(r[3]) : "r"(addr));
}

__device__ __forceinline__ void cp16(uint32_t saddr, const void* g) {
    asm volatile("cp.async.cg.shared.global [%0], [%1], 16;" :: "r"(saddr), "l"(g));
}
__device__ __forceinline__ void cp_commit() { asm volatile("cp.async.commit_group;"); }
template <int N> __device__ __forceinline__ void cp_wait() {
    asm volatile("cp.async.wait_group %0;" :: "n"(N));
}

// ---------------------------------------------------------------------------
// Fused splitter: x -> fp16 hi/lo; weights -> single fp16.
// ---------------------------------------------------------------------------
__global__ void split_all(const float4* __restrict__ x,
                          const float4* __restrict__ w0, const float4* __restrict__ w1,
                          const float4* __restrict__ w2, const float4* __restrict__ w3,
                          uint2* __restrict__ xh, uint2* __restrict__ xl,
                          uint2* __restrict__ wh)
{
    const int i = blockIdx.x * blockDim.x + threadIdx.x;
    constexpr int NX = M_ * D_ / 4;
    constexpr int NW = D_ * D_ / 4;

    if (i < NX) {
        float4 f = x[i];
        uint32_t h01, l01, h23, l23;
        split2h(f.x, f.y, h01, l01);
        split2h(f.z, f.w, h23, l23);
        xh[i] = make_uint2(h01, h23);
        xl[i] = make_uint2(l01, l23);
    } else if (i < NX + 4 * NW) {
        const int j = i - NX;
        const int wsel = j / NW;
        const int k = j - wsel * NW;
        const float4* ws[4] = {w0, w1, w2, w3};
        float4 f = ws[wsel][k];
        __half2 h01 = __floats2half2_rn(f.x, f.y);
        __half2 h23 = __floats2half2_rn(f.z, f.w);
        wh[(size_t)wsel * NW + k] =
            make_uint2(*reinterpret_cast<uint32_t*>(&h01),
                       *reinterpret_cast<uint32_t*>(&h23));
    }
}

// ---------------------------------------------------------------------------
// GEMM fp16 2-term (R13 winner): out = (Ah+Al) * Wh^T.
// MODE 0: fused QKV. Q (wsel 0) -> fp16 hi/lo; K/V (wsel 1/2) -> single fp16.
// MODE 1: single weight, fp32 row-major output.
// ---------------------------------------------------------------------------
constexpr int RS = 40;
constexpr int GEMM_TILE = 128 * RS;
constexpr int GSTAGE = 3 * GEMM_TILE;
constexpr int GEMM_SMEM = 2 * GSTAGE * 2;            // 61440 B

template <int MODE>
__global__ __launch_bounds__(256, 2)
void gemm_fp16(const __half* __restrict__ Ah_g, const __half* __restrict__ Al_g,
               const __half* __restrict__ Wh0,
               __half* __restrict__ Qh, __half* __restrict__ Ql,
               __half* __restrict__ KV,
               float* __restrict__ Of)
{
    extern __shared__ __half smem[];

    const int tid  = threadIdx.x;
    const int wid  = tid >> 5;
    const int lane = tid & 31;
    const int wm   = wid >> 2;
    const int wn   = wid & 3;
    const int lq   = lane >> 2;
    const int lr   = (lane & 3) << 1;

    int wsel, bn;
    if (MODE == 0) { wsel = blockIdx.x >> 3; bn = (blockIdx.x & 7) * 128; }
    else           { wsel = 0;               bn = blockIdx.x * 128; }
    const int bm = blockIdx.y * 128;

    const __half* Bh_g = Wh0 + (size_t)wsel * D_ * D_;

    const uint32_t sbase = smem_u32(smem);

    auto issue = [&](int k0, int s) {
#pragma unroll
        for (int i = 0; i < 6; ++i) {
            const int a    = i >> 1;              // 0=Ah 1=Al 2=Bh
            const int c    = (i & 1) * 256 + tid;
            const int row  = c >> 2;
            const int c16  = c & 3;
            const size_t go = (size_t)((a < 2 ? bm : bn) + row) * D_ + k0 + c16 * 8;
            const __half* g = (a == 0) ? Ah_g + go : (a == 1) ? Al_g + go : Bh_g + go;
            const uint32_t sa = sbase + (uint32_t)(((s * 3 + a) * GEMM_TILE
                                 + row * RS) * 2 + c16 * 16);
            cp16(sa, g);
        }
        cp_commit();
    };

    float acc[4][4][4];
#pragma unroll
    for (int i = 0; i < 4; i++)
#pragma unroll
        for (int j = 0; j < 4; j++)
#pragma unroll
            for (int r = 0; r < 4; r++) acc[i][j][r] = 0.0f;

    issue(0, 0);

    for (int kt = 0; kt < 32; ++kt) {
        const int s = kt & 1;
        cp_wait<0>();
        __syncthreads();
        if (kt < 31) issue((kt + 1) * 32, s ^ 1);

        const __half* Ahs = smem + (s * 3 + 0) * GEMM_TILE;
        const __half* Als = smem + (s * 3 + 1) * GEMM_TILE;
        const __half* Bhs = smem + (s * 3 + 2) * GEMM_TILE;

#pragma unroll
        for (int ks = 0; ks < 2; ++ks) {
            const int kb = ks * 16 + lr;

            uint32_t bh[4][2];
#pragma unroll
            for (int nt = 0; nt < 4; ++nt) {
                const int n = wn * 32 + nt * 8 + lq;
                bh[nt][0] = *(const uint32_t*)&Bhs[n * RS + kb];
                bh[nt][1] = *(const uint32_t*)&Bhs[n * RS + kb + 8];
            }

#pragma unroll
            for (int mt = 0; mt < 4; ++mt) {
                const int r = wm * 64 + mt * 16 + lq;
                uint32_t ah[4], al[4];
                ah[0] = *(const uint32_t*)&Ahs[r * RS + kb];
                ah[1] = *(const uint32_t*)&Ahs[(r + 8) * RS + kb];
                ah[2] = *(const uint32_t*)&Ahs[r * RS + kb + 8];
                ah[3] = *(const uint32_t*)&Ahs[(r + 8) * RS + kb + 8];
                al[0] = *(const uint32_t*)&Als[r * RS + kb];
                al[1] = *(const uint32_t*)&Als[(r + 8) * RS + kb];
                al[2] = *(const uint32_t*)&Als[r * RS + kb + 8];
                al[3] = *(const uint32_t*)&Als[(r + 8) * RS + kb + 8];
#pragma unroll
                for (int nt = 0; nt < 4; ++nt) {
                    mma_fp16(acc[mt][nt], ah, bh[nt]);
                    mma_fp16(acc[mt][nt], al, bh[nt]);
                }
            }
        }
    }

#pragma unroll
    for (int mt = 0; mt < 4; ++mt) {
#pragma unroll
        for (int nt = 0; nt < 4; ++nt) {
            const int n  = bn + wn * 32 + nt * 8 + lr;
            const int m0 = bm + wm * 64 + mt * 16 + lq;
#pragma unroll
            for (int half = 0; half < 2; ++half) {
                const int m = m0 + half * 8;
                const float v0 = acc[mt][nt][half * 2];
                const float v1 = acc[mt][nt][half * 2 + 1];
                if (MODE == 0) {
                    const int b_ = m >> 11;
                    const int s_ = m & 2047;
                    const int h_ = n >> 6;
                    const int d_ = n & 63;
                    const size_t off = (((size_t)(b_ * H_ + h_) * S_ + s_) << 6) + d_;
                    if (wsel == 0) {
                        uint32_t hh, ll;
                        split2h(v0, v1, hh, ll);
                        *(uint32_t*)&Qh[off] = hh;
                        *(uint32_t*)&Ql[off] = ll;
                    } else {
                        __half2 hv = __floats2half2_rn(v0, v1);
                        *(__half2*)&KV[(size_t)(wsel - 1) * M_ * D_ + off] = hv;
                    }
                } else {
                    *(float2*)&Of[(size_t)m * D_ + n] = make_float2(v0, v1);
                }
            }
        }
    }
}

// ---------------------------------------------------------------------------
// Flash attention, fp16: S = (Qh+Ql) K^T (2 MMAs), O += (Ph+Pl) V (2 MMAs).
// K, V single fp16 -> smem stage = 2 arrays; copy traffic halved.
// cp.async 3-stage pipeline, one barrier per tile. Output fp16 hi/lo.
// ---------------------------------------------------------------------------
constexpr int ARS = 72;
constexpr int ATT_TILE = 64 * ARS;                 // 4608 fp16
constexpr int ATT_SMEM = 3 * 2 * ATT_TILE * 2;     // 55296 B

__global__ void attn_mma(const __half* __restrict__ Qh_g, const __half* __restrict__ Ql_g,
                         const __half* __restrict__ K_g, const __half* __restrict__ V_g,
                         __half* __restrict__ AOh, __half* __restrict__ AOl)
{
    extern __shared__ __half asmem[];

    const int tid  = threadIdx.x;
    const int wid  = tid >> 5;
    const int lane = tid & 31;
    const int lq   = lane >> 2;
    const int c2   = (lane & 3) << 1;

    const int qt = (int)gridDim.x - 1 - (int)blockIdx.x;
    const int q0 = qt * 128;
    const int h  = blockIdx.y;
    const int b  = blockIdx.z;
    const size_t base = (size_t)(b * H_ + h) * S_ * DH_;
    const int wrow = wid * 16;

    const uint32_t sbase = smem_u32(asmem);
    const int kn_off = (lane & 7) + ((lane & 16) ? 8 : 0);
    const int kk_off = (lane & 8);
    const int vr_off = lane & 15;
    const int vc_off = (lane & 16) ? 8 : 0;

    auto issue = [&](int k0, int s) {
#pragma unroll
        for (int it = 0; it < 2; ++it) {
            const int idx = tid + it * 256;
            const int row = idx >> 3;
            const int c16 = idx & 7;
            const size_t go = base + (size_t)(k0 + row) * DH_ + c16 * 8;
            const uint32_t so = (uint32_t)(row * ARS * 2 + c16 * 16);
            cp16(sbase + (uint32_t)((s * 2 + 0) * ATT_TILE * 2) + so, K_g + go);
            cp16(sbase + (uint32_t)((s * 2 + 1) * ATT_TILE * 2) + so, V_g + go);
        }
        cp_commit();
    };

    // Q fragments (fp16 hi/lo, kept in registers)
    uint32_t qh[4][4], ql[4][4];
    {
        const __half* qhp = Qh_g + base + (size_t)(q0 + wrow + lq) * DH_;
        const __half* qlp = Ql_g + base + (size_t)(q0 + wrow + lq) * DH_;
#pragma unroll
        for (int kt = 0; kt < 4; ++kt) {
            const int c = kt * 16 + c2;
            qh[kt][0] = *(const uint32_t*)(qhp + c);
            qh[kt][1] = *(const uint32_t*)(qhp + 8 * DH_ + c);
            qh[kt][2] = *(const uint32_t*)(qhp + c + 8);
            qh[kt][3] = *(const uint32_t*)(qhp + 8 * DH_ + c + 8);
            ql[kt][0] = *(const uint32_t*)(qlp + c);
            ql[kt][1] = *(const uint32_t*)(qlp + 8 * DH_ + c);
            ql[kt][2] = *(const uint32_t*)(qlp + c + 8);
            ql[kt][3] = *(const uint32_t*)(qlp + 8 * DH_ + c + 8);
        }
    }

    float oacc[8][4];
#pragma unroll
    for (int nt = 0; nt < 8; ++nt)
#pragma unroll
        for (int r = 0; r < 4; ++r) oacc[nt][r] = 0.0f;

    float m0 = -1e30f, m1 = -1e30f, l0 = 0.0f, l1 = 0.0f;

    constexpr float scale = 0.125f;
    const int r0g = q0 + wrow + lq;
    const int r1g = r0g + 8;
    const int rmaxWarp = q0 + wrow + 15;
    const int ntiles = q0 / 64 + 2;

    issue(0, 0);
    issue(64, 1);

    for (int t = 0; t < ntiles; ++t) {
        const int s  = t % 3;
        const int k0 = t * 64;
        if (t + 1 < ntiles) cp_wait<1>();
        else                cp_wait<0>();
        __syncthreads();
        if (t + 2 < ntiles) issue((t + 2) * 64, (t + 2) % 3);

        if (k0 <= rmaxWarp) {
            const uint32_t ku = sbase + (uint32_t)((s * 2 + 0) * ATT_TILE * 2);
            const uint32_t vu = sbase + (uint32_t)((s * 2 + 1) * ATT_TILE * 2);

            // ---- S = (Qh+Ql) K^T ----
            float sc[8][4];
#pragma unroll
            for (int nt = 0; nt < 8; ++nt)
#pragma unroll
                for (int r = 0; r < 4; ++r) sc[nt][r] = 0.0f;

#pragma unroll
            for (int kt = 0; kt < 4; ++kt) {
#pragma unroll
                for (int nt2 = 0; nt2 < 4; ++nt2) {
                    const uint32_t boff =
                        (uint32_t)(((nt2 * 16 + kn_off) * ARS + kt * 16 + kk_off) * 2);
                    uint32_t k4[4];
                    ldsm4(k4, ku + boff);
                    const int nt = nt2 * 2;
                    mma_fp16(sc[nt],     qh[kt], k4);
                    mma_fp16(sc[nt],     ql[kt], k4);
                    mma_fp16(sc[nt + 1], qh[kt], k4 + 2);
                    mma_fp16(sc[nt + 1], ql[kt], k4 + 2);
                }
            }

            // ---- scale + causal mask ----
            const bool needMask = (k0 + 64 > q0 + wrow);
#pragma unroll
            for (int nt = 0; nt < 8; ++nt) {
                const int c0g = k0 + nt * 8 + c2;
                sc[nt][0] *= scale; sc[nt][1] *= scale;
                sc[nt][2] *= scale; sc[nt][3] *= scale;
                if (needMask) {
                    if (c0g     > r0g) sc[nt][0] = -1e30f;
                    if (c0g + 1 > r0g) sc[nt][1] = -1e30f;
                    if (c0g     > r1g) sc[nt][2] = -1e30f;
                    if (c0g + 1 > r1g) sc[nt][3] = -1e30f;
                }
            }

            // ---- online softmax ----
            float mx0 = -1e30f, mx1 = -1e30f;
#pragma unroll
            for (int nt = 0; nt < 8; ++nt) {
                mx0 = fmaxf(mx0, fmaxf(sc[nt][0], sc[nt][1]));
                mx1 = fmaxf(mx1, fmaxf(sc[nt][2], sc[nt][3]));
            }
            mx0 = fmaxf(mx0, __shfl_xor_sync(0xffffffffu, mx0, 1));
            mx0 = fmaxf(mx0, __shfl_xor_sync(0xffffffffu, mx0, 2));
            mx1 = fmaxf(mx1, __shfl_xor_sync(0xffffffffu, mx1, 1));
            mx1 = fmaxf(mx1, __shfl_xor_sync(0xffffffffu, mx1, 2));

            const float mn0 = fmaxf(m0, mx0);
            const float mn1 = fmaxf(m1, mx1);
            const float corr0 = __expf(m0 - mn0);
            const float corr1 = __expf(m1 - mn1);
            m0 = mn0; m1 = mn1;

            float rs0 = 0.0f, rs1 = 0.0f;
#pragma unroll
            for (int nt = 0; nt < 8; ++nt) {
                float p0 = __expf(sc[nt][0] - mn0);
                float p1 = __expf(sc[nt][1] - mn0);
                float p2 = __expf(sc[nt][2] - mn1);
                float p3 = __expf(sc[nt][3] - mn1);
                sc[nt][0] = p0; sc[nt][1] = p1; sc[nt][2] = p2; sc[nt][3] = p3;
                rs0 += p0 + p1;
                rs1 += p2 + p3;
            }
            rs0 += __shfl_xor_sync(0xffffffffu, rs0, 1);
            rs0 += __shfl_xor_sync(0xffffffffu, rs0, 2);
            rs1 += __shfl_xor_sync(0xffffffffu, rs1, 1);
            rs1 += __shfl_xor_sync(0xffffffffu, rs1, 2);
            l0 = l0 * corr0 + rs0;
            l1 = l1 * corr1 + rs1;

#pragma unroll
            for (int nt = 0; nt < 8; ++nt) {
                oacc[nt][0] *= corr0; oacc[nt][1] *= corr0;
                oacc[nt][2] *= corr1; oacc[nt][3] *= corr1;
            }

            // ---- pack P into fp16 hi/lo A-fragments ----
            uint32_t ph[4][4], pl[4][4];
#pragma unroll
            for (int kt = 0; kt < 4; ++kt) {
                const int t0 = 2 * kt, t1 = 2 * kt + 1;
                split2h(sc[t0][0], sc[t0][1], ph[kt][0], pl[kt][0]);
                split2h(sc[t0][2], sc[t0][3], ph[kt][1], pl[kt][1]);
                split2h(sc[t1][0], sc[t1][1], ph[kt][2], pl[kt][2]);
                split2h(sc[t1][2], sc[t1][3], ph[kt][3], pl[kt][3]);
            }

            // ---- O += (Ph+Pl) V ----
#pragma unroll
            for (int kt = 0; kt < 4; ++kt) {
#pragma unroll
                for (int nt2 = 0; nt2 < 4; ++nt2) {
                    const uint32_t boff =
                        (uint32_t)(((kt * 16 + vr_off) * ARS + nt2 * 16 + vc_off) * 2);
                    uint32_t v4[4];
                    ldsm4t(v4, vu + boff);
                    const int nt = nt2 * 2;
                    mma_fp16(oacc[nt],     ph[kt], v4);
                    mma_fp16(oacc[nt],     pl[kt], v4);
                    mma_fp16(oacc[nt + 1], ph[kt], v4 + 2);
                    mma_fp16(oacc[nt + 1], pl[kt], v4 + 2);
                }
            }
        }
    }

    // epilogue: normalize, write fp16 hi/lo pairs for the output GEMM
    const float inv0 = 1.0f / l0;
    const float inv1 = 1.0f / l1;
#pragma unroll
    for (int nt = 0; nt < 8; ++nt) {
        const int d = h * DH_ + nt * 8 + c2;
        uint32_t hh, ll;
        split2h(oacc[nt][0] * inv0, oacc[nt][1] * inv0, hh, ll);
        *(uint32_t*)&AOh[(size_t)(b * S_ + r0g) * D_ + d] = hh;
        *(uint32_t*)&AOl[(size_t)(b * S_ + r0g) * D_ + d] = ll;
        split2h(oacc[nt][2] * inv1, oacc[nt][3] * inv1, hh, ll);
        *(uint32_t*)&AOh[(size_t)(b * S_ + r1g) * D_ + d] = hh;
        *(uint32_t*)&AOl[(size_t)(b * S_ + r1g) * D_ + d] = ll;
    }
}

// ---------------------------------------------------------------------------
// Launch
// ---------------------------------------------------------------------------
extern "C" void kernel_launch(void* const* d_in, const int* in_sizes, int n_in,
                              void* d_out, int out_size)
{
    const float* x  = (const float*)d_in[0];
    const float* w0 = (const float*)d_in[1];
    const float* w1 = (const float*)d_in[2];
    const float* w2 = (const float*)d_in[3];
    const float* w3 = (const float*)d_in[4];
    float* out = (float*)d_out;

    void *pxh, *pxl, *pw, *pqh, *pql, *pkv, *paoh, *paol;
    cudaGetSymbolAddress(&pxh, g_xh);   cudaGetSymbolAddress(&pxl, g_xl);
    cudaGetSymbolAddress(&pw, g_w);
    cudaGetSymbolAddress(&pqh, g_qh);   cudaGetSymbolAddress(&pql, g_ql);
    cudaGetSymbolAddress(&pkv, g_kv);
    cudaGetSymbolAddress(&paoh, g_aoh); cudaGetSymbolAddress(&paol, g_aol);

    __half* xh = (__half*)pxh;   __half* xl = (__half*)pxl;
    __half* wh = (__half*)pw;
    __half* qh = (__half*)pqh;   __half* ql = (__half*)pql;
    __half* kv = (__half*)pkv;
    __half* aoh = (__half*)paoh; __half* aol = (__half*)paol;

    {
        const int ntot = M_ * D_ / 4 + 4 * (D_ * D_ / 4);
        split_all<<<(ntot + 255) / 256, 256>>>(
            (const float4*)x, (const float4*)w0, (const float4*)w1,
            (const float4*)w2, (const float4*)w3,
            (uint2*)xh, (uint2*)xl, (uint2*)wh);
    }

    cudaFuncSetAttribute(gemm_fp16<0>, cudaFuncAttributeMaxDynamicSharedMemorySize, GEMM_SMEM);
    cudaFuncSetAttribute(gemm_fp16<1>, cudaFuncAttributeMaxDynamicSharedMemorySize, GEMM_SMEM);
    cudaFuncSetAttribute(attn_mma,     cudaFuncAttributeMaxDynamicSharedMemorySize, ATT_SMEM);

    // Fused QKV: grid.x = 3 weights x 8 n-tiles
    dim3 qkv_grid(24, M_ / 128);
    gemm_fp16<0><<<qkv_grid, 256, GEMM_SMEM>>>(xh, xl, wh, qh, ql, kv, nullptr);

    dim3 attn_grid(S_ / 128, H_, B_);
    attn_mma<<<attn_grid, 256, ATT_SMEM>>>(
        qh, ql, kv, kv + (size_t)M_ * D_, aoh, aol);

    dim3 gemm_grid(D_ / 128, M_ / 128);
    gemm_fp16<1><<<gemm_grid, 256, GEMM_SMEM>>>(
        aoh, aol, wh + 3 * (size_t)D_ * D_, nullptr, nullptr, nullptr, out);
}

// round 16
// speedup vs baseline: 1.7103x; 1.1497x over previous
#include <cuda_runtime.h>
#include <cuda_fp16.h>
#include <cstdint>
#include <cstddef>

// ---------------------------------------------------------------------------
// Problem constants
// ---------------------------------------------------------------------------
constexpr int B_  = 2;
constexpr int S_  = 2048;
constexpr int D_  = 1024;
constexpr int H_  = 16;
constexpr int DH_ = 64;
constexpr int M_  = B_ * S_;   // 4096

// ---------------------------------------------------------------------------
// Scratch (all fp16)
//   x, attention-output: fp16 hi/lo pairs (GEMM A operands, 2-term)
//   weights: single fp16
//   Q/K/V: single fp16 (attention is 1-term per MMA stage)
// ---------------------------------------------------------------------------
__device__ __align__(256) __half g_xh[(size_t)M_ * D_], g_xl[(size_t)M_ * D_];
__device__ __align__(256) __half g_w[4][(size_t)D_ * D_];
__device__ __align__(256) __half g_qkv[3][(size_t)M_ * D_];    // [0]=Q,[1]=K,[2]=V
__device__ __align__(256) __half g_aoh[(size_t)M_ * D_], g_aol[(size_t)M_ * D_];

// ---------------------------------------------------------------------------
// Helpers
// ---------------------------------------------------------------------------
__device__ __forceinline__ void mma_fp16(float* c, const uint32_t* a, const uint32_t* b) {
    asm volatile(
        "mma.sync.aligned.m16n8k16.row.col.f32.f16.f16.f32 "
        "{%0,%1,%2,%3}, {%4,%5,%6,%7}, {%8,%9}, {%0,%1,%2,%3};"
        : "+f"(c[0]), "+f"(c[1]), "+f"(c[2]), "+f"(c[3])
        : "r"(a[0]), "r"(a[1]), "r"(a[2]), "r"(a[3]), "r"(b[0]), "r"(b[1]));
}

__device__ __forceinline__ void split2h(float x, float y, uint32_t& hi, uint32_t& lo) {
    __half2 h = __floats2half2_rn(x, y);
    float rx = x - __half2float(h.x);
    float ry = y - __half2float(h.y);
    __half2 l = __floats2half2_rn(rx, ry);
    hi = *reinterpret_cast<uint32_t*>(&h);
    lo = *reinterpret_cast<uint32_t*>(&l);
}

__device__ __forceinline__ uint32_t smem_u32(const void* p) {
    uint32_t a;
    asm("{ .reg .u64 t; cvta.to.shared.u64 t, %1; cvt.u32.u64 %0, t; }" : "=r"(a) : "l"(p));
    return a;
}

__device__ __forceinline__ void ldsm4(uint32_t* r, uint32_t addr) {
    asm volatile("ldmatrix.sync.aligned.m8n8.x4.shared.b16 {%0,%1,%2,%3}, [%4];"
        : "=r"(r[0]), "=r"(r[1]), "=r"(r[2]), "=r"(r[3]) : "r"(addr));
}
__device__ __forceinline__ void ldsm4t(uint32_t* r, uint32_t addr) {
    asm volatile("ldmatrix.sync.aligned.m8n8.x4.trans.shared.b16 {%0,%1,%2,%3}, [%4];"
        : "=r"(r[0]), "=r"(r[1]), "=r"(r[2]), "=r"(r[3]) : "r"(addr));
}

__device__ __forceinline__ void cp16(uint32_t saddr, const void* g) {
    asm volatile("cp.async.cg.shared.global [%0], [%1], 16;" :: "r"(saddr), "l"(g));
}
__device__ __forceinline__ void cp_commit() { asm volatile("cp.async.commit_group;"); }
template <int N> __device__ __forceinline__ void cp_wait() {
    asm volatile("cp.async.wait_group %0;" :: "n"(N));
}

// ---------------------------------------------------------------------------
// Fused splitter: x -> fp16 hi/lo; weights -> single fp16.
// ---------------------------------------------------------------------------
__global__ void split_all(const float4* __restrict__ x,
                          const float4* __restrict__ w0, const float4* __restrict__ w1,
                          const float4* __restrict__ w2, const float4* __restrict__ w3,
                          uint2* __restrict__ xh, uint2* __restrict__ xl,
                          uint2* __restrict__ wh)
{
    const int i = blockIdx.x * blockDim.x + threadIdx.x;
    constexpr int NX = M_ * D_ / 4;
    constexpr int NW = D_ * D_ / 4;

    if (i < NX) {
        float4 f = x[i];
        uint32_t h01, l01, h23, l23;
        split2h(f.x, f.y, h01, l01);
        split2h(f.z, f.w, h23, l23);
        xh[i] = make_uint2(h01, h23);
        xl[i] = make_uint2(l01, l23);
    } else if (i < NX + 4 * NW) {
        const int j = i - NX;
        const int wsel = j / NW;
        const int k = j - wsel * NW;
        const float4* ws[4] = {w0, w1, w2, w3};
        float4 f = ws[wsel][k];
        __half2 h01 = __floats2half2_rn(f.x, f.y);
        __half2 h23 = __floats2half2_rn(f.z, f.w);
        wh[(size_t)wsel * NW + k] =
            make_uint2(*reinterpret_cast<uint32_t*>(&h01),
                       *reinterpret_cast<uint32_t*>(&h23));
    }
}

// ---------------------------------------------------------------------------
// GEMM fp16 2-term: out = (Ah+Al) * Wh^T.
// MODE 0: fused QKV -> single fp16 scatter to [B,H,S,DH] (per wsel).
// MODE 1: single weight, fp32 row-major output.
// ---------------------------------------------------------------------------
constexpr int RS = 40;
constexpr int GEMM_TILE = 128 * RS;
constexpr int GSTAGE = 3 * GEMM_TILE;
constexpr int GEMM_SMEM = 2 * GSTAGE * 2;            // 61440 B

template <int MODE>
__global__ __launch_bounds__(256, 2)
void gemm_fp16(const __half* __restrict__ Ah_g, const __half* __restrict__ Al_g,
               const __half* __restrict__ Wh0,
               __half* __restrict__ QKV,
               float* __restrict__ Of)
{
    extern __shared__ __half smem[];

    const int tid  = threadIdx.x;
    const int wid  = tid >> 5;
    const int lane = tid & 31;
    const int wm   = wid >> 2;
    const int wn   = wid & 3;
    const int lq   = lane >> 2;
    const int lr   = (lane & 3) << 1;

    int wsel, bn;
    if (MODE == 0) { wsel = blockIdx.x >> 3; bn = (blockIdx.x & 7) * 128; }
    else           { wsel = 0;               bn = blockIdx.x * 128; }
    const int bm = blockIdx.y * 128;

    const __half* Bh_g = Wh0 + (size_t)wsel * D_ * D_;

    const uint32_t sbase = smem_u32(smem);

    auto issue = [&](int k0, int s) {
#pragma unroll
        for (int i = 0; i < 6; ++i) {
            const int a    = i >> 1;              // 0=Ah 1=Al 2=Bh
            const int c    = (i & 1) * 256 + tid;
            const int row  = c >> 2;
            const int c16  = c & 3;
            const size_t go = (size_t)((a < 2 ? bm : bn) + row) * D_ + k0 + c16 * 8;
            const __half* g = (a == 0) ? Ah_g + go : (a == 1) ? Al_g + go : Bh_g + go;
            const uint32_t sa = sbase + (uint32_t)(((s * 3 + a) * GEMM_TILE
                                 + row * RS) * 2 + c16 * 16);
            cp16(sa, g);
        }
        cp_commit();
    };

    float acc[4][4][4];
#pragma unroll
    for (int i = 0; i < 4; i++)
#pragma unroll
        for (int j = 0; j < 4; j++)
#pragma unroll
            for (int r = 0; r < 4; r++) acc[i][j][r] = 0.0f;

    issue(0, 0);

    for (int kt = 0; kt < 32; ++kt) {
        const int s = kt & 1;
        cp_wait<0>();
        __syncthreads();
        if (kt < 31) issue((kt + 1) * 32, s ^ 1);

        const __half* Ahs = smem + (s * 3 + 0) * GEMM_TILE;
        const __half* Als = smem + (s * 3 + 1) * GEMM_TILE;
        const __half* Bhs = smem + (s * 3 + 2) * GEMM_TILE;

#pragma unroll
        for (int ks = 0; ks < 2; ++ks) {
            const int kb = ks * 16 + lr;

            uint32_t bh[4][2];
#pragma unroll
            for (int nt = 0; nt < 4; ++nt) {
                const int n = wn * 32 + nt * 8 + lq;
                bh[nt][0] = *(const uint32_t*)&Bhs[n * RS + kb];
                bh[nt][1] = *(const uint32_t*)&Bhs[n * RS + kb + 8];
            }

#pragma unroll
            for (int mt = 0; mt < 4; ++mt) {
                const int r = wm * 64 + mt * 16 + lq;
                uint32_t ah[4], al[4];
                ah[0] = *(const uint32_t*)&Ahs[r * RS + kb];
                ah[1] = *(const uint32_t*)&Ahs[(r + 8) * RS + kb];
                ah[2] = *(const uint32_t*)&Ahs[r * RS + kb + 8];
                ah[3] = *(const uint32_t*)&Ahs[(r + 8) * RS + kb + 8];
                al[0] = *(const uint32_t*)&Als[r * RS + kb];
                al[1] = *(const uint32_t*)&Als[(r + 8) * RS + kb];
                al[2] = *(const uint32_t*)&Als[r * RS + kb + 8];
                al[3] = *(const uint32_t*)&Als[(r + 8) * RS + kb + 8];
#pragma unroll
                for (int nt = 0; nt < 4; ++nt) {
                    mma_fp16(acc[mt][nt], ah, bh[nt]);
                    mma_fp16(acc[mt][nt], al, bh[nt]);
                }
            }
        }
    }

#pragma unroll
    for (int mt = 0; mt < 4; ++mt) {
#pragma unroll
        for (int nt = 0; nt < 4; ++nt) {
            const int n  = bn + wn * 32 + nt * 8 + lr;
            const int m0 = bm + wm * 64 + mt * 16 + lq;
#pragma unroll
            for (int half = 0; half < 2; ++half) {
                const int m = m0 + half * 8;
                const float v0 = acc[mt][nt][half * 2];
                const float v1 = acc[mt][nt][half * 2 + 1];
                if (MODE == 0) {
                    const int b_ = m >> 11;
                    const int s_ = m & 2047;
                    const int h_ = n >> 6;
                    const int d_ = n & 63;
                    const size_t off = (((size_t)(b_ * H_ + h_) * S_ + s_) << 6) + d_;
                    __half2 hv = __floats2half2_rn(v0, v1);
                    *(__half2*)&QKV[(size_t)wsel * M_ * D_ + off] = hv;
                } else {
                    *(float2*)&Of[(size_t)m * D_ + n] = make_float2(v0, v1);
                }
            }
        }
    }
}

// ---------------------------------------------------------------------------
// Flash attention, fp16 1-term: S = Q K^T, O += P V (single fp16 operands).
// cp.async 3-stage K/V pipeline, one barrier per tile, 2 CTAs/SM.
// Output written as fp16 hi/lo pairs for the final 2-term GEMM.
// ---------------------------------------------------------------------------
constexpr int ARS = 72;
constexpr int ATT_TILE = 64 * ARS;                 // 4608 fp16
constexpr int ATT_SMEM = 3 * 2 * ATT_TILE * 2;     // 55296 B

__global__ __launch_bounds__(256, 2)
void attn_mma(const __half* __restrict__ Q_g,
              const __half* __restrict__ K_g, const __half* __restrict__ V_g,
              __half* __restrict__ AOh, __half* __restrict__ AOl)
{
    extern __shared__ __half asmem[];

    const int tid  = threadIdx.x;
    const int wid  = tid >> 5;
    const int lane = tid & 31;
    const int lq   = lane >> 2;
    const int c2   = (lane & 3) << 1;

    const int qt = (int)gridDim.x - 1 - (int)blockIdx.x;
    const int q0 = qt * 128;
    const int h  = blockIdx.y;
    const int b  = blockIdx.z;
    const size_t base = (size_t)(b * H_ + h) * S_ * DH_;
    const int wrow = wid * 16;

    const uint32_t sbase = smem_u32(asmem);
    const int kn_off = (lane & 7) + ((lane & 16) ? 8 : 0);
    const int kk_off = (lane & 8);
    const int vr_off = lane & 15;
    const int vc_off = (lane & 16) ? 8 : 0;

    auto issue = [&](int k0, int s) {
#pragma unroll
        for (int it = 0; it < 2; ++it) {
            const int idx = tid + it * 256;
            const int row = idx >> 3;
            const int c16 = idx & 7;
            const size_t go = base + (size_t)(k0 + row) * DH_ + c16 * 8;
            const uint32_t so = (uint32_t)(row * ARS * 2 + c16 * 16);
            cp16(sbase + (uint32_t)((s * 2 + 0) * ATT_TILE * 2) + so, K_g + go);
            cp16(sbase + (uint32_t)((s * 2 + 1) * ATT_TILE * 2) + so, V_g + go);
        }
        cp_commit();
    };

    // Q fragments (single fp16, registers)
    uint32_t qf[4][4];
    {
        const __half* qp = Q_g + base + (size_t)(q0 + wrow + lq) * DH_;
#pragma unroll
        for (int kt = 0; kt < 4; ++kt) {
            const int c = kt * 16 + c2;
            qf[kt][0] = *(const uint32_t*)(qp + c);
            qf[kt][1] = *(const uint32_t*)(qp + 8 * DH_ + c);
            qf[kt][2] = *(const uint32_t*)(qp + c + 8);
            qf[kt][3] = *(const uint32_t*)(qp + 8 * DH_ + c + 8);
        }
    }

    float oacc[8][4];
#pragma unroll
    for (int nt = 0; nt < 8; ++nt)
#pragma unroll
        for (int r = 0; r < 4; ++r) oacc[nt][r] = 0.0f;

    float m0 = -1e30f, m1 = -1e30f, l0 = 0.0f, l1 = 0.0f;

    constexpr float scale = 0.125f;
    const int r0g = q0 + wrow + lq;
    const int r1g = r0g + 8;
    const int rmaxWarp = q0 + wrow + 15;
    const int ntiles = q0 / 64 + 2;

    issue(0, 0);
    issue(64, 1);

    for (int t = 0; t < ntiles; ++t) {
        const int s  = t % 3;
        const int k0 = t * 64;
        if (t + 1 < ntiles) cp_wait<1>();
        else                cp_wait<0>();
        __syncthreads();
        if (t + 2 < ntiles) issue((t + 2) * 64, (t + 2) % 3);

        if (k0 <= rmaxWarp) {
            const uint32_t ku = sbase + (uint32_t)((s * 2 + 0) * ATT_TILE * 2);
            const uint32_t vu = sbase + (uint32_t)((s * 2 + 1) * ATT_TILE * 2);

            // ---- S = Q K^T (1 term) ----
            float sc[8][4];
#pragma unroll
            for (int nt = 0; nt < 8; ++nt)
#pragma unroll
                for (int r = 0; r < 4; ++r) sc[nt][r] = 0.0f;

#pragma unroll
            for (int kt = 0; kt < 4; ++kt) {
#pragma unroll
                for (int nt2 = 0; nt2 < 4; ++nt2) {
                    const uint32_t boff =
                        (uint32_t)(((nt2 * 16 + kn_off) * ARS + kt * 16 + kk_off) * 2);
                    uint32_t k4[4];
                    ldsm4(k4, ku + boff);
                    mma_fp16(sc[nt2 * 2],     qf[kt], k4);
                    mma_fp16(sc[nt2 * 2 + 1], qf[kt], k4 + 2);
                }
            }

            // ---- scale + causal mask ----
            const bool needMask = (k0 + 64 > q0 + wrow);
#pragma unroll
            for (int nt = 0; nt < 8; ++nt) {
                const int c0g = k0 + nt * 8 + c2;
                sc[nt][0] *= scale; sc[nt][1] *= scale;
                sc[nt][2] *= scale; sc[nt][3] *= scale;
                if (needMask) {
                    if (c0g     > r0g) sc[nt][0] = -1e30f;
                    if (c0g + 1 > r0g) sc[nt][1] = -1e30f;
                    if (c0g     > r1g) sc[nt][2] = -1e30f;
                    if (c0g + 1 > r1g) sc[nt][3] = -1e30f;
                }
            }

            // ---- online softmax ----
            float mx0 = -1e30f, mx1 = -1e30f;
#pragma unroll
            for (int nt = 0; nt < 8; ++nt) {
                mx0 = fmaxf(mx0, fmaxf(sc[nt][0], sc[nt][1]));
                mx1 = fmaxf(mx1, fmaxf(sc[nt][2], sc[nt][3]));
            }
            mx0 = fmaxf(mx0, __shfl_xor_sync(0xffffffffu, mx0, 1));
            mx0 = fmaxf(mx0, __shfl_xor_sync(0xffffffffu, mx0, 2));
            mx1 = fmaxf(mx1, __shfl_xor_sync(0xffffffffu, mx1, 1));
            mx1 = fmaxf(mx1, __shfl_xor_sync(0xffffffffu, mx1, 2));

            const float mn0 = fmaxf(m0, mx0);
            const float mn1 = fmaxf(m1, mx1);
            const float corr0 = __expf(m0 - mn0);
            const float corr1 = __expf(m1 - mn1);
            m0 = mn0; m1 = mn1;

            float rs0 = 0.0f, rs1 = 0.0f;
#pragma unroll
            for (int nt = 0; nt < 8; ++nt) {
                float p0 = __expf(sc[nt][0] - mn0);
                float p1 = __expf(sc[nt][1] - mn0);
                float p2 = __expf(sc[nt][2] - mn1);
                float p3 = __expf(sc[nt][3] - mn1);
                sc[nt][0] = p0; sc[nt][1] = p1; sc[nt][2] = p2; sc[nt][3] = p3;
                rs0 += p0 + p1;
                rs1 += p2 + p3;
            }
            rs0 += __shfl_xor_sync(0xffffffffu, rs0, 1);
            rs0 += __shfl_xor_sync(0xffffffffu, rs0, 2);
            rs1 += __shfl_xor_sync(0xffffffffu, rs1, 1);
            rs1 += __shfl_xor_sync(0xffffffffu, rs1, 2);
            l0 = l0 * corr0 + rs0;
            l1 = l1 * corr1 + rs1;

#pragma unroll
            for (int nt = 0; nt < 8; ++nt) {
                oacc[nt][0] *= corr0; oacc[nt][1] *= corr0;
                oacc[nt][2] *= corr1; oacc[nt][3] *= corr1;
            }

            // ---- pack P (single fp16) ----
            uint32_t pf[4][4];
#pragma unroll
            for (int kt = 0; kt < 4; ++kt) {
                const int t0 = 2 * kt, t1 = 2 * kt + 1;
                __half2 a = __floats2half2_rn(sc[t0][0], sc[t0][1]);
                __half2 bb = __floats2half2_rn(sc[t0][2], sc[t0][3]);
                __half2 cc = __floats2half2_rn(sc[t1][0], sc[t1][1]);
                __half2 dd = __floats2half2_rn(sc[t1][2], sc[t1][3]);
                pf[kt][0] = *reinterpret_cast<uint32_t*>(&a);
                pf[kt][1] = *reinterpret_cast<uint32_t*>(&bb);
                pf[kt][2] = *reinterpret_cast<uint32_t*>(&cc);
                pf[kt][3] = *reinterpret_cast<uint32_t*>(&dd);
            }

            // ---- O += P V (1 term) ----
#pragma unroll
            for (int kt = 0; kt < 4; ++kt) {
#pragma unroll
                for (int nt2 = 0; nt2 < 4; ++nt2) {
                    const uint32_t boff =
                        (uint32_t)(((kt * 16 + vr_off) * ARS + nt2 * 16 + vc_off) * 2);
                    uint32_t v4[4];
                    ldsm4t(v4, vu + boff);
                    mma_fp16(oacc[nt2 * 2],     pf[kt], v4);
                    mma_fp16(oacc[nt2 * 2 + 1], pf[kt], v4 + 2);
                }
            }
        }
    }

    // epilogue: normalize, write fp16 hi/lo pairs for the output GEMM
    const float inv0 = 1.0f / l0;
    const float inv1 = 1.0f / l1;
#pragma unroll
    for (int nt = 0; nt < 8; ++nt) {
        const int d = h * DH_ + nt * 8 + c2;
        uint32_t hh, ll;
        split2h(oacc[nt][0] * inv0, oacc[nt][1] * inv0, hh, ll);
        *(uint32_t*)&AOh[(size_t)(b * S_ + r0g) * D_ + d] = hh;
        *(uint32_t*)&AOl[(size_t)(b * S_ + r0g) * D_ + d] = ll;
        split2h(oacc[nt][2] * inv1, oacc[nt][3] * inv1, hh, ll);
        *(uint32_t*)&AOh[(size_t)(b * S_ + r1g) * D_ + d] = hh;
        *(uint32_t*)&AOl[(size_t)(b * S_ + r1g) * D_ + d] = ll;
    }
}

// ---------------------------------------------------------------------------
// Launch
// ---------------------------------------------------------------------------
extern "C" void kernel_launch(void* const* d_in, const int* in_sizes, int n_in,
                              void* d_out, int out_size)
{
    const float* x  = (const float*)d_in[0];
    const float* w0 = (const float*)d_in[1];
    const float* w1 = (const float*)d_in[2];
    const float* w2 = (const float*)d_in[3];
    const float* w3 = (const float*)d_in[4];
    float* out = (float*)d_out;

    void *pxh, *pxl, *pw, *pqkv, *paoh, *paol;
    cudaGetSymbolAddress(&pxh, g_xh);   cudaGetSymbolAddress(&pxl, g_xl);
    cudaGetSymbolAddress(&pw, g_w);
    cudaGetSymbolAddress(&pqkv, g_qkv);
    cudaGetSymbolAddress(&paoh, g_aoh); cudaGetSymbolAddress(&paol, g_aol);

    __half* xh = (__half*)pxh;   __half* xl = (__half*)pxl;
    __half* wh = (__half*)pw;
    __half* qkv = (__half*)pqkv;
    __half* aoh = (__half*)paoh; __half* aol = (__half*)paol;

    {
        const int ntot = M_ * D_ / 4 + 4 * (D_ * D_ / 4);
        split_all<<<(ntot + 255) / 256, 256>>>(
            (const float4*)x, (const float4*)w0, (const float4*)w1,
            (const float4*)w2, (const float4*)w3,
            (uint2*)xh, (uint2*)xl, (uint2*)wh);
    }

    cudaFuncSetAttribute(gemm_fp16<0>, cudaFuncAttributeMaxDynamicSharedMemorySize, GEMM_SMEM);
    cudaFuncSetAttribute(gemm_fp16<1>, cudaFuncAttributeMaxDynamicSharedMemorySize, GEMM_SMEM);
    cudaFuncSetAttribute(attn_mma,     cudaFuncAttributeMaxDynamicSharedMemorySize, ATT_SMEM);

    // Fused QKV: grid.x = 3 weights x 8 n-tiles
    dim3 qkv_grid(24, M_ / 128);
    gemm_fp16<0><<<qkv_grid, 256, GEMM_SMEM>>>(xh, xl, wh, qkv, nullptr);

    dim3 attn_grid(S_ / 128, H_, B_);
    attn_mma<<<attn_grid, 256, ATT_SMEM>>>(
        qkv, qkv + (size_t)M_ * D_, qkv + 2 * (size_t)M_ * D_, aoh, aol);

    dim3 gemm_grid(D_ / 128, M_ / 128);
    gemm_fp16<1><<<gemm_grid, 256, GEMM_SMEM>>>(
        aoh, aol, wh + 3 * (size_t)D_ * D_, nullptr, out);
}

// round 17
// speedup vs baseline: 2.3903x; 1.3976x over previous
#include <cuda_runtime.h>
#include <cuda_fp16.h>
#include <cstdint>
#include <cstddef>

// ---------------------------------------------------------------------------
// Problem constants
// ---------------------------------------------------------------------------
constexpr int B_  = 2;
constexpr int S_  = 2048;
constexpr int D_  = 1024;
constexpr int H_  = 16;
constexpr int DH_ = 64;
constexpr int M_  = B_ * S_;   // 4096

// ---------------------------------------------------------------------------
// Scratch: everything single fp16 (1-term numerics throughout)
// ---------------------------------------------------------------------------
__device__ __align__(256) __half g_x16[(size_t)M_ * D_];
__device__ __align__(256) __half g_w[4][(size_t)D_ * D_];
__device__ __align__(256) __half g_qkv[3][(size_t)M_ * D_];    // [0]=Q,[1]=K,[2]=V
__device__ __align__(256) __half g_ao[(size_t)M_ * D_];

// ---------------------------------------------------------------------------
// Helpers
// ---------------------------------------------------------------------------
__device__ __forceinline__ void mma_fp16(float* c, const uint32_t* a, const uint32_t* b) {
    asm volatile(
        "mma.sync.aligned.m16n8k16.row.col.f32.f16.f16.f32 "
        "{%0,%1,%2,%3}, {%4,%5,%6,%7}, {%8,%9}, {%0,%1,%2,%3};"
        : "+f"(c[0]), "+f"(c[1]), "+f"(c[2]), "+f"(c[3])
        : "r"(a[0]), "r"(a[1]), "r"(a[2]), "r"(a[3]), "r"(b[0]), "r"(b[1]));
}

__device__ __forceinline__ uint32_t smem_u32(const void* p) {
    uint32_t a;
    asm("{ .reg .u64 t; cvta.to.shared.u64 t, %1; cvt.u32.u64 %0, t; }" : "=r"(a) : "l"(p));
    return a;
}

__device__ __forceinline__ void ldsm4(uint32_t* r, uint32_t addr) {
    asm volatile("ldmatrix.sync.aligned.m8n8.x4.shared.b16 {%0,%1,%2,%3}, [%4];"
        : "=r"(r[0]), "=r"(r[1]), "=r"(r[2]), "=r"(r[3]) : "r"(addr));
}
__device__ __forceinline__ void ldsm4t(uint32_t* r, uint32_t addr) {
    asm volatile("ldmatrix.sync.aligned.m8n8.x4.trans.shared.b16 {%0,%1,%2,%3}, [%4];"
        : "=r"(r[0]), "=r"(r[1]), "=r"(r[2]), "=r"(r[3]) : "r"(addr));
}

__device__ __forceinline__ void cp16(uint32_t saddr, const void* g) {
    asm volatile("cp.async.cg.shared.global [%0], [%1], 16;" :: "r"(saddr), "l"(g));
}
__device__ __forceinline__ void cp_commit() { asm volatile("cp.async.commit_group;"); }
template <int N> __device__ __forceinline__ void cp_wait() {
    asm volatile("cp.async.wait_group %0;" :: "n"(N));
}

// ---------------------------------------------------------------------------
// Fused converter: x and all weights -> single fp16.
// ---------------------------------------------------------------------------
__global__ void conv_all(const float4* __restrict__ x,
                         const float4* __restrict__ w0, const float4* __restrict__ w1,
                         const float4* __restrict__ w2, const float4* __restrict__ w3,
                         uint2* __restrict__ x16, uint2* __restrict__ wh)
{
    const int i = blockIdx.x * blockDim.x + threadIdx.x;
    constexpr int NX = M_ * D_ / 4;
    constexpr int NW = D_ * D_ / 4;

    const float4* src;
    uint2* dst;
    if (i < NX) {
        src = x + i; dst = x16 + i;
    } else if (i < NX + 4 * NW) {
        const int j = i - NX;
        const int wsel = j / NW;
        const int k = j - wsel * NW;
        const float4* ws[4] = {w0, w1, w2, w3};
        src = ws[wsel] + k;
        dst = wh + (size_t)wsel * NW + k;
    } else {
        return;
    }
    float4 f = *src;
    __half2 h01 = __floats2half2_rn(f.x, f.y);
    __half2 h23 = __floats2half2_rn(f.z, f.w);
    *dst = make_uint2(*reinterpret_cast<uint32_t*>(&h01),
                      *reinterpret_cast<uint32_t*>(&h23));
}

// ---------------------------------------------------------------------------
// GEMM fp16 1-term: out = A16 * W16^T.
// Tile 128x128x32, 8 warps, warp 64x32, cp.async 2-stage, one barrier/k-iter.
// smem/stage: [A][B] each 128*40 fp16; 2 stages = 40960 B.
// MODE 0: fused QKV -> fp16 scatter to [B,H,S,DH].  MODE 1: fp32 out.
// ---------------------------------------------------------------------------
constexpr int RS = 40;
constexpr int GEMM_TILE = 128 * RS;
constexpr int GSTAGE = 2 * GEMM_TILE;
constexpr int GEMM_SMEM = 2 * GSTAGE * 2;            // 40960 B

template <int MODE>
__global__ __launch_bounds__(256, 2)
void gemm_fp16(const __half* __restrict__ A_g, const __half* __restrict__ Wh0,
               __half* __restrict__ QKV, float* __restrict__ Of)
{
    extern __shared__ __half smem[];

    const int tid  = threadIdx.x;
    const int wid  = tid >> 5;
    const int lane = tid & 31;
    const int wm   = wid >> 2;
    const int wn   = wid & 3;
    const int lq   = lane >> 2;
    const int lr   = (lane & 3) << 1;

    int wsel, bn;
    if (MODE == 0) { wsel = blockIdx.x >> 3; bn = (blockIdx.x & 7) * 128; }
    else           { wsel = 0;               bn = blockIdx.x * 128; }
    const int bm = blockIdx.y * 128;

    const __half* B_g = Wh0 + (size_t)wsel * D_ * D_;

    const uint32_t sbase = smem_u32(smem);

    auto issue = [&](int k0, int s) {
#pragma unroll
        for (int i = 0; i < 4; ++i) {
            const int a    = i >> 1;              // 0=A 1=B
            const int c    = (i & 1) * 256 + tid; // 0..511
            const int row  = c >> 2;
            const int c16  = c & 3;
            const size_t go = (size_t)((a == 0 ? bm : bn) + row) * D_ + k0 + c16 * 8;
            const __half* g = (a == 0) ? A_g + go : B_g + go;
            const uint32_t sa = sbase + (uint32_t)(((s * 2 + a) * GEMM_TILE
                                 + row * RS) * 2 + c16 * 16);
            cp16(sa, g);
        }
        cp_commit();
    };

    float acc[4][4][4];
#pragma unroll
    for (int i = 0; i < 4; i++)
#pragma unroll
        for (int j = 0; j < 4; j++)
#pragma unroll
            for (int r = 0; r < 4; r++) acc[i][j][r] = 0.0f;

    issue(0, 0);

    for (int kt = 0; kt < 32; ++kt) {
        const int s = kt & 1;
        cp_wait<0>();
        __syncthreads();
        if (kt < 31) issue((kt + 1) * 32, s ^ 1);

        const __half* As = smem + (s * 2 + 0) * GEMM_TILE;
        const __half* Bs = smem + (s * 2 + 1) * GEMM_TILE;

#pragma unroll
        for (int ks = 0; ks < 2; ++ks) {
            const int kb = ks * 16 + lr;

            uint32_t bh[4][2];
#pragma unroll
            for (int nt = 0; nt < 4; ++nt) {
                const int n = wn * 32 + nt * 8 + lq;
                bh[nt][0] = *(const uint32_t*)&Bs[n * RS + kb];
                bh[nt][1] = *(const uint32_t*)&Bs[n * RS + kb + 8];
            }

#pragma unroll
            for (int mt = 0; mt < 4; ++mt) {
                const int r = wm * 64 + mt * 16 + lq;
                uint32_t ah[4];
                ah[0] = *(const uint32_t*)&As[r * RS + kb];
                ah[1] = *(const uint32_t*)&As[(r + 8) * RS + kb];
                ah[2] = *(const uint32_t*)&As[r * RS + kb + 8];
                ah[3] = *(const uint32_t*)&As[(r + 8) * RS + kb + 8];
#pragma unroll
                for (int nt = 0; nt < 4; ++nt)
                    mma_fp16(acc[mt][nt], ah, bh[nt]);
            }
        }
    }

#pragma unroll
    for (int mt = 0; mt < 4; ++mt) {
#pragma unroll
        for (int nt = 0; nt < 4; ++nt) {
            const int n  = bn + wn * 32 + nt * 8 + lr;
            const int m0 = bm + wm * 64 + mt * 16 + lq;
#pragma unroll
            for (int half = 0; half < 2; ++half) {
                const int m = m0 + half * 8;
                const float v0 = acc[mt][nt][half * 2];
                const float v1 = acc[mt][nt][half * 2 + 1];
                if (MODE == 0) {
                    const int b_ = m >> 11;
                    const int s_ = m & 2047;
                    const int h_ = n >> 6;
                    const int d_ = n & 63;
                    const size_t off = (((size_t)(b_ * H_ + h_) * S_ + s_) << 6) + d_;
                    __half2 hv = __floats2half2_rn(v0, v1);
                    *(__half2*)&QKV[(size_t)wsel * M_ * D_ + off] = hv;
                } else {
                    *(float2*)&Of[(size_t)m * D_ + n] = make_float2(v0, v1);
                }
            }
        }
    }
}

// ---------------------------------------------------------------------------
// Flash attention, fp16 1-term (R16 winner), output single fp16.
// cp.async 3-stage K/V pipeline, one barrier per tile, 2 CTAs/SM.
// ---------------------------------------------------------------------------
constexpr int ARS = 72;
constexpr int ATT_TILE = 64 * ARS;                 // 4608 fp16
constexpr int ATT_SMEM = 3 * 2 * ATT_TILE * 2;     // 55296 B

__global__ __launch_bounds__(256, 2)
void attn_mma(const __half* __restrict__ Q_g,
              const __half* __restrict__ K_g, const __half* __restrict__ V_g,
              __half* __restrict__ AO)
{
    extern __shared__ __half asmem[];

    const int tid  = threadIdx.x;
    const int wid  = tid >> 5;
    const int lane = tid & 31;
    const int lq   = lane >> 2;
    const int c2   = (lane & 3) << 1;

    const int qt = (int)gridDim.x - 1 - (int)blockIdx.x;
    const int q0 = qt * 128;
    const int h  = blockIdx.y;
    const int b  = blockIdx.z;
    const size_t base = (size_t)(b * H_ + h) * S_ * DH_;
    const int wrow = wid * 16;

    const uint32_t sbase = smem_u32(asmem);
    const int kn_off = (lane & 7) + ((lane & 16) ? 8 : 0);
    const int kk_off = (lane & 8);
    const int vr_off = lane & 15;
    const int vc_off = (lane & 16) ? 8 : 0;

    auto issue = [&](int k0, int s) {
#pragma unroll
        for (int it = 0; it < 2; ++it) {
            const int idx = tid + it * 256;
            const int row = idx >> 3;
            const int c16 = idx & 7;
            const size_t go = base + (size_t)(k0 + row) * DH_ + c16 * 8;
            const uint32_t so = (uint32_t)(row * ARS * 2 + c16 * 16);
            cp16(sbase + (uint32_t)((s * 2 + 0) * ATT_TILE * 2) + so, K_g + go);
            cp16(sbase + (uint32_t)((s * 2 + 1) * ATT_TILE * 2) + so, V_g + go);
        }
        cp_commit();
    };

    // Q fragments (single fp16, registers)
    uint32_t qf[4][4];
    {
        const __half* qp = Q_g + base + (size_t)(q0 + wrow + lq) * DH_;
#pragma unroll
        for (int kt = 0; kt < 4; ++kt) {
            const int c = kt * 16 + c2;
            qf[kt][0] = *(const uint32_t*)(qp + c);
            qf[kt][1] = *(const uint32_t*)(qp + 8 * DH_ + c);
            qf[kt][2] = *(const uint32_t*)(qp + c + 8);
            qf[kt][3] = *(const uint32_t*)(qp + 8 * DH_ + c + 8);
        }
    }

    float oacc[8][4];
#pragma unroll
    for (int nt = 0; nt < 8; ++nt)
#pragma unroll
        for (int r = 0; r < 4; ++r) oacc[nt][r] = 0.0f;

    float m0 = -1e30f, m1 = -1e30f, l0 = 0.0f, l1 = 0.0f;

    constexpr float scale = 0.125f;
    const int r0g = q0 + wrow + lq;
    const int r1g = r0g + 8;
    const int rmaxWarp = q0 + wrow + 15;
    const int ntiles = q0 / 64 + 2;

    issue(0, 0);
    issue(64, 1);

    for (int t = 0; t < ntiles; ++t) {
        const int s  = t % 3;
        const int k0 = t * 64;
        if (t + 1 < ntiles) cp_wait<1>();
        else                cp_wait<0>();
        __syncthreads();
        if (t + 2 < ntiles) issue((t + 2) * 64, (t + 2) % 3);

        if (k0 <= rmaxWarp) {
            const uint32_t ku = sbase + (uint32_t)((s * 2 + 0) * ATT_TILE * 2);
            const uint32_t vu = sbase + (uint32_t)((s * 2 + 1) * ATT_TILE * 2);

            // ---- S = Q K^T ----
            float sc[8][4];
#pragma unroll
            for (int nt = 0; nt < 8; ++nt)
#pragma unroll
                for (int r = 0; r < 4; ++r) sc[nt][r] = 0.0f;

#pragma unroll
            for (int kt = 0; kt < 4; ++kt) {
#pragma unroll
                for (int nt2 = 0; nt2 < 4; ++nt2) {
                    const uint32_t boff =
                        (uint32_t)(((nt2 * 16 + kn_off) * ARS + kt * 16 + kk_off) * 2);
                    uint32_t k4[4];
                    ldsm4(k4, ku + boff);
                    mma_fp16(sc[nt2 * 2],     qf[kt], k4);
                    mma_fp16(sc[nt2 * 2 + 1], qf[kt], k4 + 2);
                }
            }

            // ---- scale + causal mask ----
            const bool needMask = (k0 + 64 > q0 + wrow);
#pragma unroll
            for (int nt = 0; nt < 8; ++nt) {
                const int c0g = k0 + nt * 8 + c2;
                sc[nt][0] *= scale; sc[nt][1] *= scale;
                sc[nt][2] *= scale; sc[nt][3] *= scale;
                if (needMask) {
                    if (c0g     > r0g) sc[nt][0] = -1e30f;
                    if (c0g + 1 > r0g) sc[nt][1] = -1e30f;
                    if (c0g     > r1g) sc[nt][2] = -1e30f;
                    if (c0g + 1 > r1g) sc[nt][3] = -1e30f;
                }
            }

            // ---- online softmax ----
            float mx0 = -1e30f, mx1 = -1e30f;
#pragma unroll
            for (int nt = 0; nt < 8; ++nt) {
                mx0 = fmaxf(mx0, fmaxf(sc[nt][0], sc[nt][1]));
                mx1 = fmaxf(mx1, fmaxf(sc[nt][2], sc[nt][3]));
            }
            mx0 = fmaxf(mx0, __shfl_xor_sync(0xffffffffu, mx0, 1));
            mx0 = fmaxf(mx0, __shfl_xor_sync(0xffffffffu, mx0, 2));
            mx1 = fmaxf(mx1, __shfl_xor_sync(0xffffffffu, mx1, 1));
            mx1 = fmaxf(mx1, __shfl_xor_sync(0xffffffffu, mx1, 2));

            const float mn0 = fmaxf(m0, mx0);
            const float mn1 = fmaxf(m1, mx1);
            const float corr0 = __expf(m0 - mn0);
            const float corr1 = __expf(m1 - mn1);
            m0 = mn0; m1 = mn1;

            float rs0 = 0.0f, rs1 = 0.0f;
#pragma unroll
            for (int nt = 0; nt < 8; ++nt) {
                float p0 = __expf(sc[nt][0] - mn0);
                float p1 = __expf(sc[nt][1] - mn0);
                float p2 = __expf(sc[nt][2] - mn1);
                float p3 = __expf(sc[nt][3] - mn1);
                sc[nt][0] = p0; sc[nt][1] = p1; sc[nt][2] = p2; sc[nt][3] = p3;
                rs0 += p0 + p1;
                rs1 += p2 + p3;
            }
            rs0 += __shfl_xor_sync(0xffffffffu, rs0, 1);
            rs0 += __shfl_xor_sync(0xffffffffu, rs0, 2);
            rs1 += __shfl_xor_sync(0xffffffffu, rs1, 1);
            rs1 += __shfl_xor_sync(0xffffffffu, rs1, 2);
            l0 = l0 * corr0 + rs0;
            l1 = l1 * corr1 + rs1;

#pragma unroll
            for (int nt = 0; nt < 8; ++nt) {
                oacc[nt][0] *= corr0; oacc[nt][1] *= corr0;
                oacc[nt][2] *= corr1; oacc[nt][3] *= corr1;
            }

            // ---- pack P (single fp16) ----
            uint32_t pf[4][4];
#pragma unroll
            for (int kt = 0; kt < 4; ++kt) {
                const int t0 = 2 * kt, t1 = 2 * kt + 1;
                __half2 a  = __floats2half2_rn(sc[t0][0], sc[t0][1]);
                __half2 bb = __floats2half2_rn(sc[t0][2], sc[t0][3]);
                __half2 cc = __floats2half2_rn(sc[t1][0], sc[t1][1]);
                __half2 dd = __floats2half2_rn(sc[t1][2], sc[t1][3]);
                pf[kt][0] = *reinterpret_cast<uint32_t*>(&a);
                pf[kt][1] = *reinterpret_cast<uint32_t*>(&bb);
                pf[kt][2] = *reinterpret_cast<uint32_t*>(&cc);
                pf[kt][3] = *reinterpret_cast<uint32_t*>(&dd);
            }

            // ---- O += P V ----
#pragma unroll
            for (int kt = 0; kt < 4; ++kt) {
#pragma unroll
                for (int nt2 = 0; nt2 < 4; ++nt2) {
                    const uint32_t boff =
                        (uint32_t)(((kt * 16 + vr_off) * ARS + nt2 * 16 + vc_off) * 2);
                    uint32_t v4[4];
                    ldsm4t(v4, vu + boff);
                    mma_fp16(oacc[nt2 * 2],     pf[kt], v4);
                    mma_fp16(oacc[nt2 * 2 + 1], pf[kt], v4 + 2);
                }
            }
        }
    }

    // epilogue: normalize, write single fp16 [B,S,D]
    const float inv0 = 1.0f / l0;
    const float inv1 = 1.0f / l1;
#pragma unroll
    for (int nt = 0; nt < 8; ++nt) {
        const int d = h * DH_ + nt * 8 + c2;
        __half2 r0 = __floats2half2_rn(oacc[nt][0] * inv0, oacc[nt][1] * inv0);
        __half2 r1 = __floats2half2_rn(oacc[nt][2] * inv1, oacc[nt][3] * inv1);
        *(__half2*)&AO[(size_t)(b * S_ + r0g) * D_ + d] = r0;
        *(__half2*)&AO[(size_t)(b * S_ + r1g) * D_ + d] = r1;
    }
}

// ---------------------------------------------------------------------------
// Launch
// ---------------------------------------------------------------------------
extern "C" void kernel_launch(void* const* d_in, const int* in_sizes, int n_in,
                              void* d_out, int out_size)
{
    const float* x  = (const float*)d_in[0];
    const float* w0 = (const float*)d_in[1];
    const float* w1 = (const float*)d_in[2];
    const float* w2 = (const float*)d_in[3];
    const float* w3 = (const float*)d_in[4];
    float* out = (float*)d_out;

    void *px16, *pw, *pqkv, *pao;
    cudaGetSymbolAddress(&px16, g_x16);
    cudaGetSymbolAddress(&pw, g_w);
    cudaGetSymbolAddress(&pqkv, g_qkv);
    cudaGetSymbolAddress(&pao, g_ao);

    __half* x16 = (__half*)px16;
    __half* wh  = (__half*)pw;
    __half* qkv = (__half*)pqkv;
    __half* ao  = (__half*)pao;

    {
        const int ntot = M_ * D_ / 4 + 4 * (D_ * D_ / 4);
        conv_all<<<(ntot + 255) / 256, 256>>>(
            (const float4*)x, (const float4*)w0, (const float4*)w1,
            (const float4*)w2, (const float4*)w3,
            (uint2*)x16, (uint2*)wh);
    }

    cudaFuncSetAttribute(gemm_fp16<0>, cudaFuncAttributeMaxDynamicSharedMemorySize, GEMM_SMEM);
    cudaFuncSetAttribute(gemm_fp16<1>, cudaFuncAttributeMaxDynamicSharedMemorySize, GEMM_SMEM);
    cudaFuncSetAttribute(attn_mma,     cudaFuncAttributeMaxDynamicSharedMemorySize, ATT_SMEM);

    // Fused QKV: grid.x = 3 weights x 8 n-tiles
    dim3 qkv_grid(24, M_ / 128);
    gemm_fp16<0><<<qkv_grid, 256, GEMM_SMEM>>>(x16, wh, qkv, nullptr);

    dim3 attn_grid(S_ / 128, H_, B_);
    attn_mma<<<attn_grid, 256, ATT_SMEM>>>(
        qkv, qkv + (size_t)M_ * D_, qkv + 2 * (size_t)M_ * D_, ao);

    dim3 gemm_grid(D_ / 128, M_ / 128);
    gemm_fp16<1><<<gemm_grid, 256, GEMM_SMEM>>>(
        ao, wh + 3 * (size_t)D_ * D_, nullptr, out);
}